// round 3
// baseline (speedup 1.0000x reference)
#include <cuda_runtime.h>
#include <math.h>
#include <stdint.h>

#define B_ 8
#define T_ 16
#define N_ 1024
#define CS 48
#define GS 32
#define HH 150
#define G3 450
#define ONUM 1024
#define MAXA 160
#define MAXM 80
#define NTA 256
#define NTB 512
#define MAXHIT 16

// ------------- device scratch (no cudaMalloc allowed) -------------
__device__ float g_gi[B_*T_*MAXM*G3];     // GRU input gates at m1 rows
__device__ float g_h23[B_*T_*MAXM*HH];    // attention hidden at m23 rows
__device__ float g_om23[B_*T_*HH];        // gated max-pool over m23 rows
__device__ int   g_c1[B_*T_];
__device__ int   g_c23[B_*T_];
__device__ short g_m1i[B_*T_*MAXM];
__device__ short g_m23i[B_*T_*MAXM];

__device__ __forceinline__ unsigned fenc(float f){
    unsigned u = __float_as_uint(f);
    return (u & 0x80000000u) ? ~u : (u | 0x80000000u);
}
__device__ __forceinline__ float fdec(unsigned u){
    return (u & 0x80000000u) ? __uint_as_float(u ^ 0x80000000u) : __uint_as_float(~u);
}

// ---------------- Phase A smem float offsets ----------------
#define AW_G 0        // 1536  Wg (48x32)
#define AW_Q 1536     // 1024  Wq
#define AW_K 2560     // 1024  Wk
#define AW_V 3584     // 4800  Wv (32x150)
#define AB_G 8384     // 32
#define AB_Q 8416     // 32
#define AB_K 8448     // 32
#define AB_V 8480     // 160 (150 used)
#define A_OM 8640     // 160 (unsigned encoded max)
#define A_EC 8800     // 15360  E_cur (320x48)
#define A_EP 24160    // 15360  E_prev
#define A_IN 39520    // 7680   in48 (160x48)
#define A_NP 47200    // 3840 + 480 pad  np (80x48)
#define A_TOTF 51520
// overlays (after stages retire)
#define A_CO 8800     // co 160x32
#define A_QR 13920    // qrows 80x32
#define A_Qb 24160    // q 80x32
#define A_Kb 26720    // k 80x32
#define A_Pb 29280    // P 80x80
#define A_Vb 39520    // v 80x150 (over IN+NP+pad = 12000)
// int16 region at byte 206080, flags at 209888, cnts at 209968; total 210000 B

__global__ void __launch_bounds__(NTA) phaseA(
    const float* __restrict__ code_x, const float* __restrict__ divided,
    const float* __restrict__ neighbors, const float* __restrict__ adj,
    const float* __restrict__ c_emb, const float* __restrict__ n_emb,
    const float* __restrict__ u_emb,
    const float* __restrict__ Wg, const float* __restrict__ bg,
    const float* __restrict__ Wi, const float* __restrict__ bi,
    const float* __restrict__ Wq, const float* __restrict__ bq,
    const float* __restrict__ Wk, const float* __restrict__ bk,
    const float* __restrict__ Wv, const float* __restrict__ bv)
{
    extern __shared__ float sm[];
    short* sh      = (short*)((char*)sm + A_TOTF*4);
    short* rowmap  = sh;              // 1024
    short* idxA    = sh + 1024;       // 160
    short* idxNb   = idxA + MAXA;
    short* idxAp   = idxNb + MAXA;
    short* idxNbp  = idxAp + MAXA;
    short* m1l     = idxNbp + MAXA;   // 80
    short* m23l    = m1l + MAXM;      // 80
    short* aiof1   = m23l + MAXM;     // 80
    unsigned char* flags = (unsigned char*)((char*)sm + 209888); // 80
    int* cnts      = (int*)((char*)sm + 209968);                 // 8

    const int bt = blockIdx.x;
    const int b  = bt >> 4, t = bt & 15;
    const int tid = threadIdx.x, lane = tid & 31, wid = tid >> 5;

    // ---- weights / biases into smem; init OM to encoded -inf ----
    for (int i = tid; i < CS*GS; i += NTA) sm[AW_G + i] = Wg[i];
    for (int i = tid; i < GS*GS; i += NTA) { sm[AW_Q + i] = Wq[i]; sm[AW_K + i] = Wk[i]; }
    for (int i = tid; i < GS*HH; i += NTA) sm[AW_V + i] = Wv[i];
    if (tid < GS) { sm[AB_G + tid] = bg[tid]; sm[AB_Q + tid] = bq[tid]; sm[AB_K + tid] = bk[tid]; }
    for (int i = tid; i < HH; i += NTA) sm[AB_V + i] = bv[i];
    {
        unsigned negenc = fenc(-1e30f);
        for (int i = tid; i < 160; i += NTA) ((unsigned*)(sm + A_OM))[i] = negenc;
    }

    // ---- ordered list building via warp ballots ----
    if (wid == 0) {
        int cAa = 0, cNbv = 0, cc1 = 0, cc23 = 0;
        const int base0 = bt * N_;
        const unsigned lt = (1u << lane) - 1u;
        for (int base = 0; base < N_; base += 32) {
            int n = base + lane;
            float cx  = code_x[base0 + n];
            float m1v = divided[(base0 + n)*3 + 0];
            float m2v = divided[(base0 + n)*3 + 1];
            float m3v = divided[(base0 + n)*3 + 2];
            float nbv = neighbors[base0 + n];
            unsigned mk = __ballot_sync(0xffffffffu, cx > 0.f);
            if (cx > 0.f) { int p = cAa + __popc(mk & lt); if (p < MAXA) { idxA[p] = (short)n; rowmap[n] = (short)p; } }
            cAa += __popc(mk);
            mk = __ballot_sync(0xffffffffu, nbv > 0.f);
            if (nbv > 0.f) { int p = cNbv + __popc(mk & lt); if (p < MAXA) idxNb[p] = (short)n; }
            cNbv += __popc(mk);
            mk = __ballot_sync(0xffffffffu, m1v > 0.f);
            if (m1v > 0.f) { int p = cc1 + __popc(mk & lt); if (p < MAXM) m1l[p] = (short)n; }
            cc1 += __popc(mk);
            bool e23 = (m2v > 0.f) || (m3v > 0.f);
            mk = __ballot_sync(0xffffffffu, e23);
            if (e23) { int p = cc23 + __popc(mk & lt); if (p < MAXM) { m23l[p] = (short)n; flags[p] = (m2v > 0.f) ? 1 : 0; } }
            cc23 += __popc(mk);
        }
        if (lane == 0) { cnts[0] = min(cAa, MAXA); cnts[1] = min(cNbv, MAXA);
                         cnts[4] = min(cc1, MAXM); cnts[5] = min(cc23, MAXM); }
    } else if (wid == 1) {
        if (t > 0) {
            int cAp = 0, cNbp = 0;
            const int base0 = (bt - 1) * N_;
            const unsigned lt = (1u << lane) - 1u;
            for (int base = 0; base < N_; base += 32) {
                int n = base + lane;
                float cx  = code_x[base0 + n];
                float nbv = neighbors[base0 + n];
                unsigned mk = __ballot_sync(0xffffffffu, cx > 0.f);
                if (cx > 0.f) { int p = cAp + __popc(mk & lt); if (p < MAXA) idxAp[p] = (short)n; }
                cAp += __popc(mk);
                mk = __ballot_sync(0xffffffffu, nbv > 0.f);
                if (nbv > 0.f) { int p = cNbp + __popc(mk & lt); if (p < MAXA) idxNbp[p] = (short)n; }
                cNbp += __popc(mk);
            }
            if (lane == 0) { cnts[2] = min(cAp, MAXA); cnts[3] = min(cNbp, MAXA); }
        } else if (lane == 0) { cnts[2] = 0; cnts[3] = 0; }
    }
    __syncthreads();

    const int cA = cnts[0], cNb = cnts[1], cAp = cnts[2], cNbp = cnts[3];
    const int c1 = cnts[4], c23 = cnts[5];
    const int totC = cA + cNb, totP = cAp + cNbp;

    // lists to global; flags nb_prev gate; aiof1; embedding staging
    if (tid == 0) { g_c1[bt] = c1; g_c23[bt] = c23; }
    for (int i = tid; i < c1;  i += NTA) g_m1i[bt*MAXM + i]  = m1l[i];
    for (int i = tid; i < c23; i += NTA) g_m23i[bt*MAXM + i] = m23l[i];
    if (t > 0)
        for (int i = tid; i < c23; i += NTA)
            if ((flags[i] & 1) && neighbors[(bt - 1)*N_ + m23l[i]] > 0.f) flags[i] |= 2;
    {
        int c1p = (c1 + 7) & ~7;
        for (int i = tid; i < c1p; i += NTA) aiof1[i] = (i < c1) ? rowmap[m1l[i]] : (short)0;
    }
    for (int task = tid; task < totC*CS; task += NTA) {
        int j = task / CS, c = task - j*CS;
        int n = (j < cA) ? idxA[j] : idxNb[j - cA];
        sm[A_EC + task] = (j < cA) ? c_emb[n*CS + c] : n_emb[n*CS + c];
    }
    if (t > 0)
        for (int task = tid; task < totP*CS; task += NTA) {
            int j = task / CS, c = task - j*CS;
            int n = (j < cAp) ? idxAp[j] : idxNbp[j - cAp];
            sm[A_EP + task] = (j < cAp) ? c_emb[n*CS + c] : n_emb[n*CS + c];
        }
    __syncthreads();

    // ---- S1: GraphLayer aggregation input at active rows ----
    for (int task = tid; task < cA*4; task += NTA) {
        int ai = task >> 2, ch = (task & 3) * 12;
        int m = idxA[ai];
        const float* arow = adj + (size_t)m * N_;
        float acc[12];
        const float* e0 = sm + A_EC + ai*CS + ch;
        #pragma unroll
        for (int c = 0; c < 12; c++) acc[c] = e0[c];
        for (int j = 0; j < totC; j++) {
            int n = (j < cA) ? idxA[j] : idxNb[j - cA];
            float a = __ldg(arow + n);
            if (a != 0.f) {
                const float* er = sm + A_EC + j*CS + ch;
                #pragma unroll
                for (int c = 0; c < 12; c++) acc[c] += a * er[c];
            }
        }
        float* o = sm + A_IN + ai*CS + ch;
        #pragma unroll
        for (int c = 0; c < 12; c++) o[c] = acc[c];
    }
    // ---- S1b: no_{t-1} input at m2 rows (gated by prev neighbor mask) ----
    if (t > 0)
        for (int task = tid; task < c23*4; task += NTA) {
            int mi = task >> 2, ch = (task & 3) * 12;
            float acc[12];
            #pragma unroll
            for (int c = 0; c < 12; c++) acc[c] = 0.f;
            if (flags[mi] & 2) {
                int m = m23l[mi];
                const float* arow = adj + (size_t)m * N_;
                const float* nr = n_emb + m*CS + ch;
                #pragma unroll
                for (int c = 0; c < 12; c++) acc[c] = nr[c];
                for (int j = 0; j < totP; j++) {
                    int n = (j < cAp) ? idxAp[j] : idxNbp[j - cAp];
                    float a = __ldg(arow + n);
                    if (a != 0.f) {
                        const float* er = sm + A_EP + j*CS + ch;
                        #pragma unroll
                        for (int c = 0; c < 12; c++) acc[c] += a * er[c];
                    }
                }
            }
            float* o = sm + A_NP + mi*CS + ch;
            #pragma unroll
            for (int c = 0; c < 12; c++) o[c] = acc[c];
        }
    __syncthreads();

    // ---- S2: co = lrelu(in48 @ Wg + bg); qrows ----
    for (int task = tid; task < cA*GS; task += NTA) {
        int ai = task >> 5, g = task & 31;
        float acc = sm[AB_G + g];
        const float* in = sm + A_IN + ai*CS;
        #pragma unroll 8
        for (int c = 0; c < CS; c++) acc += in[c] * sm[AW_G + c*GS + g];
        sm[A_CO + task] = acc > 0.f ? acc : 0.01f * acc;
    }
    if (t > 0)
        for (int task = tid; task < c23*GS; task += NTA) {
            int mi = task >> 5, g = task & 31;
            float v;
            if (flags[mi] & 1) {
                float acc = sm[AB_G + g];
                const float* in = sm + A_NP + mi*CS;
                #pragma unroll 8
                for (int c = 0; c < CS; c++) acc += in[c] * sm[AW_G + c*GS + g];
                v = acc > 0.f ? acc : 0.01f * acc;
            } else {
                v = u_emb[m23l[mi]*GS + g];
            }
            sm[A_QR + task] = v;
        }
    __syncthreads();

    // ---- S3: gi (always), q/k/v (t>0) ----
    if (c1 > 0) {
        int ng = (c1 + 7) >> 3;
        for (int task = tid; task < G3*ng; task += NTA) {
            int j = task % G3, grp = task / G3, r0 = grp * 8;
            float acc[8];
            int ai[8];
            #pragma unroll
            for (int g = 0; g < 8; g++) { acc[g] = 0.f; ai[g] = aiof1[r0 + g]; }
            for (int c = 0; c < GS; c++) {
                float w = __ldg(Wi + c*G3 + j);
                #pragma unroll
                for (int g = 0; g < 8; g++) acc[g] += sm[A_CO + ai[g]*GS + c] * w;
            }
            float bij = __ldg(bi + j);
            int nr = min(8, c1 - r0);
            #pragma unroll
            for (int g = 0; g < 8; g++)
                if (g < nr) g_gi[(bt*MAXM + r0 + g)*G3 + j] = acc[g] + bij;
        }
    }
    if (t > 0 && c23 > 0) {
        for (int task = tid; task < c23*GS; task += NTA) {
            int i = task >> 5, a = task & 31;
            const float* qr = sm + A_QR + i*GS;
            int ai = rowmap[m23l[i]];
            const float* co = sm + A_CO + ai*GS;
            float accq = sm[AB_Q + a], acck = sm[AB_K + a];
            #pragma unroll
            for (int g = 0; g < GS; g++) {
                accq += qr[g] * sm[AW_Q + g*GS + a];
                acck += co[g] * sm[AW_K + g*GS + a];
            }
            sm[A_Qb + task] = accq;
            sm[A_Kb + task] = acck;
        }
        for (int task = tid; task < c23*HH; task += NTA) {
            int i = task / HH, h = task - i*HH;
            const float* qr = sm + A_QR + i*GS;
            float acc = sm[AB_V + h];
            #pragma unroll
            for (int g = 0; g < GS; g++) acc += qr[g] * sm[AW_V + g*HH + h];
            sm[A_Vb + i*HH + h] = acc;
        }
    }
    __syncthreads();

    // ---- S4: scores + softmax (warp per query) ----
    if (t > 0 && c23 > 0) {
        const float scale = 0.17677669529663687f;  // 1/sqrt(32)
        for (int i = wid; i < c23; i += 8) {
            const float* qi = sm + A_Qb + i*GS;
            float mx = -1e30f;
            for (int j = lane; j < c23; j += 32) {
                const float* kj = sm + A_Kb + j*GS;
                float s = 0.f;
                #pragma unroll
                for (int g = 0; g < GS; g++) s += qi[g] * kj[g];
                s *= scale;
                sm[A_Pb + i*MAXM + j] = s;
                mx = fmaxf(mx, s);
            }
            for (int o = 16; o; o >>= 1) mx = fmaxf(mx, __shfl_xor_sync(0xffffffffu, mx, o));
            float sum = 0.f;
            for (int j = lane; j < c23; j += 32) {
                float e = __expf(sm[A_Pb + i*MAXM + j] - mx);
                sm[A_Pb + i*MAXM + j] = e; sum += e;
            }
            for (int o = 16; o; o >>= 1) sum += __shfl_xor_sync(0xffffffffu, sum, o);
            float inv = 1.f / sum;
            for (int j = lane; j < c23; j += 32) sm[A_Pb + i*MAXM + j] *= inv;
        }
    }
    __syncthreads();

    // ---- S5: h_m23 + om23 ----
    if (t > 0 && c23 > 0) {
        unsigned* OM = (unsigned*)(sm + A_OM);
        for (int task = tid; task < c23*HH; task += NTA) {
            int i = task / HH, h = task - i*HH;
            float acc = 0.f;
            const float* pr = sm + A_Pb + i*MAXM;
            for (int j = 0; j < c23; j++) acc += pr[j] * sm[A_Vb + j*HH + h];
            float hv = tanhf(acc);
            g_h23[(bt*MAXM + i)*HH + h] = hv;
            atomicMax(OM + h, fenc(hv));
        }
        __syncthreads();
        for (int h = tid; h < HH; h += NTA) g_om23[bt*HH + h] = fdec(((unsigned*)(sm + A_OM))[h]);
    } else {
        for (int h = tid; h < HH; h += NTA) g_om23[bt*HH + h] = 0.f;
    }
}

// ---------------- Phase B smem float offsets ----------------
#define B_HST 0        // 24000  compact h store (160x150)
#define B_HM1 24000    // 12000  h_m1 (80x150)
#define B_GHB 36000    // 7200   gh for hits (16x450)
#define B_HPB 43200    // 1200   h_prev gather (8x150); reused as pooled later
#define B_BHS 44400    // 464    bh
#define B_OUT 44864    // 2400   outs (16x150)
#define B_TMP 47264    // 512
#define B_VU  47776    // 16
#define B_SCR 47792    // 16
#define B_TOTF 47808
// shorts at byte 191232; ints at 194112; total 194128 B

__global__ void __launch_bounds__(NTB) phaseB(
    const int* __restrict__ lens,
    const float* __restrict__ Wh, const float* __restrict__ bh,
    const float* __restrict__ Wd, const float* __restrict__ bd,
    const float* __restrict__ context,
    const float* __restrict__ Wc, const float* __restrict__ bc,
    float* __restrict__ out)
{
    extern __shared__ float sm[];
    short* map     = (short*)((char*)sm + B_TOTF*4);
    short* rowsl   = map + 1024;      // 160
    short* m1L     = rowsl + 160;     // 80
    short* m23L    = m1L + 80;        // 80
    short* hitslot = m23L + 80;       // 80
    short* hslot   = hitslot + 80;    // 16
    int* ints      = (int*)((char*)sm + 194112);  // [0]=nh [1]=nrows

    const int b = blockIdx.x, tid = threadIdx.x;

    for (int i = tid; i < N_; i += NTB) map[i] = -1;
    for (int i = tid; i < G3; i += NTB) sm[B_BHS + i] = bh[i];
    if (tid == 0) ints[1] = 0;
    __syncthreads();

    for (int t = 0; t < T_; t++) {
        const int bt = b*T_ + t;
        const int c1 = g_c1[bt], c23 = g_c23[bt];
        for (int i = tid; i < c1;  i += NTB) m1L[i]  = g_m1i[bt*MAXM + i];
        for (int i = tid; i < c23; i += NTB) m23L[i] = g_m23i[bt*MAXM + i];
        __syncthreads();
        // hit detection (row has nonzero h_prev)
        if (tid == 0) {
            int nh = 0;
            for (int r = 0; r < c1; r++) {
                short s = map[m1L[r]];
                if (s >= 0 && nh < MAXHIT) { hitslot[r] = (short)nh; hslot[nh] = s; nh++; }
                else hitslot[r] = -1;
            }
            ints[0] = nh;
        }
        __syncthreads();
        const int nh = ints[0];
        const int rounds = (nh + 7) >> 3;
        for (int rd = 0; rd < rounds; rd++) {
            int nr = min(8, nh - rd*8);
            for (int task = tid; task < nr*HH; task += NTB) {
                int g = task / HH, k = task - g*HH;
                sm[B_HPB + g*HH + k] = sm[B_HST + hslot[rd*8 + g]*HH + k];
            }
            __syncthreads();
            if (tid < G3) {
                float acc[8];
                #pragma unroll
                for (int g = 0; g < 8; g++) acc[g] = 0.f;
                const float* whcol = Wh + tid;
                for (int k = 0; k < HH; k++) {
                    float w = __ldg(whcol + k*G3);
                    #pragma unroll
                    for (int g = 0; g < 8; g++) acc[g] += sm[B_HPB + g*HH + k] * w;
                }
                for (int g = 0; g < nr; g++) sm[B_GHB + (rd*8 + g)*G3 + tid] = acc[g];
            }
            __syncthreads();
        }
        // GRU gates at m1 rows
        const float* giB = g_gi + (size_t)bt * MAXM * G3;
        for (int task = tid; task < c1*HH; task += NTB) {
            int r = task / HH, h = task - r*HH;
            int hs = hitslot[r];
            float ghr, ghz, ghn, hp;
            if (hs >= 0) {
                const float* g0 = sm + B_GHB + hs*G3;
                ghr = sm[B_BHS + h]       + g0[h];
                ghz = sm[B_BHS + 150 + h] + g0[150 + h];
                ghn = sm[B_BHS + 300 + h] + g0[300 + h];
                hp  = sm[B_HST + map[m1L[r]]*HH + h];
            } else {
                ghr = sm[B_BHS + h]; ghz = sm[B_BHS + 150 + h]; ghn = sm[B_BHS + 300 + h]; hp = 0.f;
            }
            const float* gir = giB + r*G3;
            float rr = 1.f / (1.f + __expf(-(gir[h] + ghr)));
            float zz = 1.f / (1.f + __expf(-(gir[150 + h] + ghz)));
            float nn = tanhf(gir[300 + h] + rr * ghn);
            sm[B_HM1 + task] = (1.f - zz) * nn + zz * hp;
        }
        __syncthreads();
        // outs = gated om1 + om23; clear old map
        for (int h = tid; h < HH; h += NTB) {
            float mx = -1e30f;
            for (int r = 0; r < c1; r++) mx = fmaxf(mx, sm[B_HM1 + r*HH + h]);
            float o1 = (c1 > 0) ? mx : 0.f;
            sm[B_OUT + t*HH + h] = o1 + g_om23[bt*HH + h];
        }
        const int oldn = ints[1];
        for (int i = tid; i < oldn; i += NTB) map[rowsl[i]] = -1;
        __syncthreads();
        // rebuild compact store
        const int newn = c1 + ((t > 0) ? c23 : 0);
        for (int task = tid; task < newn*HH; task += NTB) {
            int s = task / HH, h = task - s*HH;
            sm[B_HST + task] = (s < c1) ? sm[B_HM1 + s*HH + h]
                                        : g_h23[(bt*MAXM + (s - c1))*HH + h];
        }
        for (int i = tid; i < newn; i += NTB) {
            short m = (i < c1) ? m1L[i] : m23L[i - c1];
            rowsl[i] = m; map[m] = (short)i;
        }
        if (tid == 0) ints[1] = newn;
        __syncthreads();
    }

    // ---- visit attention + classifier ----
    for (int task = tid; task < T_*GS; task += NTB) {
        int tt = task >> 5, a = task & 31;
        float acc = __ldg(bd + a);
        const float* o = sm + B_OUT + tt*HH;
        for (int h = 0; h < HH; h++) acc += o[h] * __ldg(Wd + h*GS + a);
        sm[B_TMP + task] = acc;
    }
    __syncthreads();
    if (tid < T_) {
        float acc = 0.f;
        for (int a = 0; a < GS; a++) acc += sm[B_TMP + tid*GS + a] * __ldg(context + a);
        sm[B_VU + tid] = acc;
    }
    __syncthreads();
    if (tid < 32) {
        int L = lens[b];
        float v = (tid < T_ && tid < L) ? sm[B_VU + tid] : -1e30f;
        float mx = v;
        for (int o = 16; o; o >>= 1) mx = fmaxf(mx, __shfl_xor_sync(0xffffffffu, mx, o));
        float e = (tid < T_ && tid < L) ? __expf(v - mx) : 0.f;
        float s = e;
        for (int o = 16; o; o >>= 1) s += __shfl_xor_sync(0xffffffffu, s, o);
        if (tid < T_) sm[B_SCR + tid] = e / s;
    }
    __syncthreads();
    for (int h = tid; h < HH; h += NTB) {
        float acc = 0.f;
        for (int tt = 0; tt < T_; tt++) acc += sm[B_SCR + tt] * sm[B_OUT + tt*HH + h];
        sm[B_HPB + h] = acc;   // pooled
    }
    __syncthreads();
    for (int o = tid; o < ONUM; o += NTB) {
        float acc = __ldg(bc + o);
        for (int h = 0; h < HH; h++) acc += sm[B_HPB + h] * __ldg(Wc + h*ONUM + o);
        out[b*ONUM + o] = 1.f / (1.f + __expf(-acc));
    }
}

extern "C" void kernel_launch(void* const* d_in, const int* in_sizes, int n_in,
                              void* d_out, int out_size)
{
    const float* code_x    = (const float*)d_in[0];
    const float* divided   = (const float*)d_in[1];
    const float* neighbors = (const float*)d_in[2];
    const int*   lens      = (const int*)d_in[3];
    const float* adj       = (const float*)d_in[4];
    const float* c_emb     = (const float*)d_in[5];
    const float* n_emb     = (const float*)d_in[6];
    const float* u_emb     = (const float*)d_in[7];
    const float* Wg = (const float*)d_in[8];  const float* bg = (const float*)d_in[9];
    const float* Wi = (const float*)d_in[10]; const float* bi = (const float*)d_in[11];
    const float* Wh = (const float*)d_in[12]; const float* bh = (const float*)d_in[13];
    const float* Wq = (const float*)d_in[14]; const float* bq = (const float*)d_in[15];
    const float* Wk = (const float*)d_in[16]; const float* bk = (const float*)d_in[17];
    const float* Wv = (const float*)d_in[18]; const float* bv = (const float*)d_in[19];
    const float* Wd = (const float*)d_in[20]; const float* bd = (const float*)d_in[21];
    const float* context = (const float*)d_in[22];
    const float* Wc = (const float*)d_in[23]; const float* bc = (const float*)d_in[24];
    float* out = (float*)d_out;

    cudaFuncSetAttribute(phaseA, cudaFuncAttributeMaxDynamicSharedMemorySize, 210000);
    cudaFuncSetAttribute(phaseB, cudaFuncAttributeMaxDynamicSharedMemorySize, 194200);

    phaseA<<<B_*T_, NTA, 210000>>>(code_x, divided, neighbors, adj, c_emb, n_emb, u_emb,
                                   Wg, bg, Wi, bi, Wq, bq, Wk, bk, Wv, bv);
    phaseB<<<B_, NTB, 194200>>>(lens, Wh, bh, Wd, bd, context, Wc, bc, out);
}

// round 4
// speedup vs baseline: 1.1121x; 1.1121x over previous
#include <cuda_runtime.h>
#include <math.h>
#include <stdint.h>

#define B_ 8
#define T_ 16
#define N_ 1024
#define CS 48
#define GS 32
#define HH 150
#define G3 450
#define ONUM 1024
#define MAXA 160
#define MAXM 80
#define NTA 256
#define NTB 512
#define MAXHIT 64

// ------------- device scratch (no cudaMalloc allowed) -------------
__device__ float g_gi[B_*T_*MAXM*G3];     // GRU input gates at m1 rows
__device__ float g_h23[B_*T_*MAXM*HH];    // attention hidden at m23 rows
__device__ float g_om23[B_*T_*HH];        // gated max-pool over m23 rows
__device__ int   g_c1[B_*T_];
__device__ int   g_c23[B_*T_];
__device__ short g_m1i[B_*T_*MAXM];
__device__ short g_m23i[B_*T_*MAXM];
__device__ float g_WhT[G3*152];           // Wh transposed [450][152], rows padded

__device__ __forceinline__ unsigned fenc(float f){
    unsigned u = __float_as_uint(f);
    return (u & 0x80000000u) ? ~u : (u | 0x80000000u);
}
__device__ __forceinline__ float fdec(unsigned u){
    return (u & 0x80000000u) ? __uint_as_float(u ^ 0x80000000u) : __uint_as_float(~u);
}

// ---------------- Wh transpose (one-off, trivial) ----------------
__global__ void transWh(const float* __restrict__ Wh) {
    int idx = blockIdx.x * blockDim.x + threadIdx.x;
    if (idx < G3 * 152) {
        int j = idx / 152, k = idx - j * 152;
        g_WhT[idx] = (k < HH) ? Wh[k * G3 + j] : 0.f;
    }
}

// ---------------- Phase A smem float offsets ----------------
#define AW_G 0        // 1536  Wg (48x32)
#define AW_Q 1536     // 1024  Wq
#define AW_K 2560     // 1024  Wk
#define AW_V 3584     // 4800  Wv (32x150)
#define AB_G 8384     // 32
#define AB_Q 8416     // 32
#define AB_K 8448     // 32
#define AB_V 8480     // 160 (150 used)
#define A_OM 8640     // 160 (unsigned encoded max)
#define A_EC 8800     // 15360  E_cur (320x48)
#define A_EP 24160    // 15360  E_prev
#define A_IN 39520    // 7680   in48 (160x48)
#define A_NP 47200    // 3840 + 480 pad  np (80x48)
#define A_TOTF 51520
// overlays (after stages retire)
#define A_CO 8800     // co 160x32
#define A_QR 13920    // qrows 80x32
#define A_Qb 24160    // q 80x32
#define A_Kb 26720    // k 80x32
#define A_Pb 29280    // P 80x80
#define A_Vb 39520    // v 80x150 (over IN+NP+pad = 12000)
// int16 region at byte 206080, flags at 209888, cnts at 209968; total 210000 B

__global__ void __launch_bounds__(NTA) phaseA(
    const float* __restrict__ code_x, const float* __restrict__ divided,
    const float* __restrict__ neighbors, const float* __restrict__ adj,
    const float* __restrict__ c_emb, const float* __restrict__ n_emb,
    const float* __restrict__ u_emb,
    const float* __restrict__ Wg, const float* __restrict__ bg,
    const float* __restrict__ Wi, const float* __restrict__ bi,
    const float* __restrict__ Wq, const float* __restrict__ bq,
    const float* __restrict__ Wk, const float* __restrict__ bk,
    const float* __restrict__ Wv, const float* __restrict__ bv)
{
    extern __shared__ float sm[];
    short* sh      = (short*)((char*)sm + A_TOTF*4);
    short* rowmap  = sh;              // 1024
    short* idxA    = sh + 1024;       // 160
    short* idxNb   = idxA + MAXA;
    short* idxAp   = idxNb + MAXA;
    short* idxNbp  = idxAp + MAXA;
    short* m1l     = idxNbp + MAXA;   // 80
    short* m23l    = m1l + MAXM;      // 80
    short* aiof1   = m23l + MAXM;     // 80
    unsigned char* flags = (unsigned char*)sm + 209888; // 80
    int* cnts      = (int*)((char*)sm + 209968);        // 8

    const int bt = blockIdx.x;
    const int t = bt & 15;
    const int tid = threadIdx.x, lane = tid & 31, wid = tid >> 5;

    // ---- weights / biases into smem; init OM to encoded -inf ----
    for (int i = tid; i < CS*GS; i += NTA) sm[AW_G + i] = Wg[i];
    for (int i = tid; i < GS*GS; i += NTA) { sm[AW_Q + i] = Wq[i]; sm[AW_K + i] = Wk[i]; }
    for (int i = tid; i < GS*HH; i += NTA) sm[AW_V + i] = Wv[i];
    if (tid < GS) { sm[AB_G + tid] = bg[tid]; sm[AB_Q + tid] = bq[tid]; sm[AB_K + tid] = bk[tid]; }
    for (int i = tid; i < HH; i += NTA) sm[AB_V + i] = bv[i];
    {
        unsigned negenc = fenc(-1e30f);
        for (int i = tid; i < 160; i += NTA) ((unsigned*)(sm + A_OM))[i] = negenc;
    }

    // ---- ordered list building via warp ballots ----
    if (wid == 0) {
        int cAa = 0, cNbv = 0, cc1 = 0, cc23 = 0;
        const int base0 = bt * N_;
        const unsigned lt = (1u << lane) - 1u;
        for (int base = 0; base < N_; base += 32) {
            int n = base + lane;
            float cx  = code_x[base0 + n];
            float m1v = divided[(base0 + n)*3 + 0];
            float m2v = divided[(base0 + n)*3 + 1];
            float m3v = divided[(base0 + n)*3 + 2];
            float nbv = neighbors[base0 + n];
            unsigned mk = __ballot_sync(0xffffffffu, cx > 0.f);
            if (cx > 0.f) { int p = cAa + __popc(mk & lt); if (p < MAXA) { idxA[p] = (short)n; rowmap[n] = (short)p; } }
            cAa += __popc(mk);
            mk = __ballot_sync(0xffffffffu, nbv > 0.f);
            if (nbv > 0.f) { int p = cNbv + __popc(mk & lt); if (p < MAXA) idxNb[p] = (short)n; }
            cNbv += __popc(mk);
            mk = __ballot_sync(0xffffffffu, m1v > 0.f);
            if (m1v > 0.f) { int p = cc1 + __popc(mk & lt); if (p < MAXM) m1l[p] = (short)n; }
            cc1 += __popc(mk);
            bool e23 = (m2v > 0.f) || (m3v > 0.f);
            mk = __ballot_sync(0xffffffffu, e23);
            if (e23) { int p = cc23 + __popc(mk & lt); if (p < MAXM) { m23l[p] = (short)n; flags[p] = (m2v > 0.f) ? 1 : 0; } }
            cc23 += __popc(mk);
        }
        if (lane == 0) { cnts[0] = min(cAa, MAXA); cnts[1] = min(cNbv, MAXA);
                         cnts[4] = min(cc1, MAXM); cnts[5] = min(cc23, MAXM); }
    } else if (wid == 1) {
        if (t > 0) {
            int cAp = 0, cNbp = 0;
            const int base0 = (bt - 1) * N_;
            const unsigned lt = (1u << lane) - 1u;
            for (int base = 0; base < N_; base += 32) {
                int n = base + lane;
                float cx  = code_x[base0 + n];
                float nbv = neighbors[base0 + n];
                unsigned mk = __ballot_sync(0xffffffffu, cx > 0.f);
                if (cx > 0.f) { int p = cAp + __popc(mk & lt); if (p < MAXA) idxAp[p] = (short)n; }
                cAp += __popc(mk);
                mk = __ballot_sync(0xffffffffu, nbv > 0.f);
                if (nbv > 0.f) { int p = cNbp + __popc(mk & lt); if (p < MAXA) idxNbp[p] = (short)n; }
                cNbp += __popc(mk);
            }
            if (lane == 0) { cnts[2] = min(cAp, MAXA); cnts[3] = min(cNbp, MAXA); }
        } else if (lane == 0) { cnts[2] = 0; cnts[3] = 0; }
    }
    __syncthreads();

    const int cA = cnts[0], cNb = cnts[1], cAp = cnts[2], cNbp = cnts[3];
    const int c1 = cnts[4], c23 = cnts[5];
    const int totC = cA + cNb, totP = cAp + cNbp;

    if (tid == 0) { g_c1[bt] = c1; g_c23[bt] = c23; }
    for (int i = tid; i < c1;  i += NTA) g_m1i[bt*MAXM + i]  = m1l[i];
    for (int i = tid; i < c23; i += NTA) g_m23i[bt*MAXM + i] = m23l[i];
    if (t > 0)
        for (int i = tid; i < c23; i += NTA)
            if ((flags[i] & 1) && neighbors[(bt - 1)*N_ + m23l[i]] > 0.f) flags[i] |= 2;
    {
        int c1p = (c1 + 7) & ~7;
        for (int i = tid; i < c1p; i += NTA) aiof1[i] = (i < c1) ? rowmap[m1l[i]] : (short)0;
    }
    for (int task = tid; task < totC*CS; task += NTA) {
        int j = task / CS, c = task - j*CS;
        int n = (j < cA) ? idxA[j] : idxNb[j - cA];
        sm[A_EC + task] = (j < cA) ? c_emb[n*CS + c] : n_emb[n*CS + c];
    }
    if (t > 0)
        for (int task = tid; task < totP*CS; task += NTA) {
            int j = task / CS, c = task - j*CS;
            int n = (j < cAp) ? idxAp[j] : idxNbp[j - cAp];
            sm[A_EP + task] = (j < cAp) ? c_emb[n*CS + c] : n_emb[n*CS + c];
        }
    __syncthreads();

    // ---- S1: GraphLayer aggregation input at active rows ----
    for (int task = tid; task < cA*4; task += NTA) {
        int ai = task >> 2, ch = (task & 3) * 12;
        int m = idxA[ai];
        const float* arow = adj + (size_t)m * N_;
        float acc[12];
        const float* e0 = sm + A_EC + ai*CS + ch;
        #pragma unroll
        for (int c = 0; c < 12; c++) acc[c] = e0[c];
        for (int j = 0; j < totC; j++) {
            int n = (j < cA) ? idxA[j] : idxNb[j - cA];
            float a = __ldg(arow + n);
            if (a != 0.f) {
                const float* er = sm + A_EC + j*CS + ch;
                #pragma unroll
                for (int c = 0; c < 12; c++) acc[c] += a * er[c];
            }
        }
        float* o = sm + A_IN + ai*CS + ch;
        #pragma unroll
        for (int c = 0; c < 12; c++) o[c] = acc[c];
    }
    // ---- S1b: no_{t-1} input at m2 rows (gated by prev neighbor mask) ----
    if (t > 0)
        for (int task = tid; task < c23*4; task += NTA) {
            int mi = task >> 2, ch = (task & 3) * 12;
            float acc[12];
            #pragma unroll
            for (int c = 0; c < 12; c++) acc[c] = 0.f;
            if (flags[mi] & 2) {
                int m = m23l[mi];
                const float* arow = adj + (size_t)m * N_;
                const float* nr = n_emb + m*CS + ch;
                #pragma unroll
                for (int c = 0; c < 12; c++) acc[c] = nr[c];
                for (int j = 0; j < totP; j++) {
                    int n = (j < cAp) ? idxAp[j] : idxNbp[j - cAp];
                    float a = __ldg(arow + n);
                    if (a != 0.f) {
                        const float* er = sm + A_EP + j*CS + ch;
                        #pragma unroll
                        for (int c = 0; c < 12; c++) acc[c] += a * er[c];
                    }
                }
            }
            float* o = sm + A_NP + mi*CS + ch;
            #pragma unroll
            for (int c = 0; c < 12; c++) o[c] = acc[c];
        }
    __syncthreads();

    // ---- S2: co = lrelu(in48 @ Wg + bg); qrows ----
    for (int task = tid; task < cA*GS; task += NTA) {
        int ai = task >> 5, g = task & 31;
        float acc = sm[AB_G + g];
        const float* in = sm + A_IN + ai*CS;
        #pragma unroll 8
        for (int c = 0; c < CS; c++) acc += in[c] * sm[AW_G + c*GS + g];
        sm[A_CO + task] = acc > 0.f ? acc : 0.01f * acc;
    }
    if (t > 0)
        for (int task = tid; task < c23*GS; task += NTA) {
            int mi = task >> 5, g = task & 31;
            float v;
            if (flags[mi] & 1) {
                float acc = sm[AB_G + g];
                const float* in = sm + A_NP + mi*CS;
                #pragma unroll 8
                for (int c = 0; c < CS; c++) acc += in[c] * sm[AW_G + c*GS + g];
                v = acc > 0.f ? acc : 0.01f * acc;
            } else {
                v = u_emb[m23l[mi]*GS + g];
            }
            sm[A_QR + task] = v;
        }
    __syncthreads();

    // ---- S3: gi (always), q/k/v (t>0) ----
    if (c1 > 0) {
        int ng = (c1 + 7) >> 3;
        for (int task = tid; task < G3*ng; task += NTA) {
            int j = task % G3, grp = task / G3, r0 = grp * 8;
            float acc[8];
            int ai[8];
            #pragma unroll
            for (int g = 0; g < 8; g++) { acc[g] = 0.f; ai[g] = aiof1[r0 + g]; }
            for (int c = 0; c < GS; c++) {
                float w = __ldg(Wi + c*G3 + j);
                #pragma unroll
                for (int g = 0; g < 8; g++) acc[g] += sm[A_CO + ai[g]*GS + c] * w;
            }
            float bij = __ldg(bi + j);
            int nr = min(8, c1 - r0);
            #pragma unroll
            for (int g = 0; g < 8; g++)
                if (g < nr) g_gi[(bt*MAXM + r0 + g)*G3 + j] = acc[g] + bij;
        }
    }
    if (t > 0 && c23 > 0) {
        for (int task = tid; task < c23*GS; task += NTA) {
            int i = task >> 5, a = task & 31;
            const float* qr = sm + A_QR + i*GS;
            int ai = rowmap[m23l[i]];
            const float* co = sm + A_CO + ai*GS;
            float accq = sm[AB_Q + a], acck = sm[AB_K + a];
            #pragma unroll
            for (int g = 0; g < GS; g++) {
                accq += qr[g] * sm[AW_Q + g*GS + a];
                acck += co[g] * sm[AW_K + g*GS + a];
            }
            sm[A_Qb + task] = accq;
            sm[A_Kb + task] = acck;
        }
        for (int task = tid; task < c23*HH; task += NTA) {
            int i = task / HH, h = task - i*HH;
            const float* qr = sm + A_QR + i*GS;
            float acc = sm[AB_V + h];
            #pragma unroll
            for (int g = 0; g < GS; g++) acc += qr[g] * sm[AW_V + g*HH + h];
            sm[A_Vb + i*HH + h] = acc;
        }
    }
    __syncthreads();

    // ---- S4: scores + softmax (warp per query) ----
    if (t > 0 && c23 > 0) {
        const float scale = 0.17677669529663687f;  // 1/sqrt(32)
        for (int i = wid; i < c23; i += 8) {
            const float* qi = sm + A_Qb + i*GS;
            float mx = -1e30f;
            for (int j = lane; j < c23; j += 32) {
                const float* kj = sm + A_Kb + j*GS;
                float s = 0.f;
                #pragma unroll
                for (int g = 0; g < GS; g++) s += qi[g] * kj[g];
                s *= scale;
                sm[A_Pb + i*MAXM + j] = s;
                mx = fmaxf(mx, s);
            }
            for (int o = 16; o; o >>= 1) mx = fmaxf(mx, __shfl_xor_sync(0xffffffffu, mx, o));
            float sum = 0.f;
            for (int j = lane; j < c23; j += 32) {
                float e = __expf(sm[A_Pb + i*MAXM + j] - mx);
                sm[A_Pb + i*MAXM + j] = e; sum += e;
            }
            for (int o = 16; o; o >>= 1) sum += __shfl_xor_sync(0xffffffffu, sum, o);
            float inv = 1.f / sum;
            for (int j = lane; j < c23; j += 32) sm[A_Pb + i*MAXM + j] *= inv;
        }
    }
    __syncthreads();

    // ---- S5: h_m23 + om23 ----
    if (t > 0 && c23 > 0) {
        unsigned* OM = (unsigned*)(sm + A_OM);
        for (int task = tid; task < c23*HH; task += NTA) {
            int i = task / HH, h = task - i*HH;
            float acc = 0.f;
            const float* pr = sm + A_Pb + i*MAXM;
            for (int j = 0; j < c23; j++) acc += pr[j] * sm[A_Vb + j*HH + h];
            float hv = tanhf(acc);
            g_h23[(bt*MAXM + i)*HH + h] = hv;
            atomicMax(OM + h, fenc(hv));
        }
        __syncthreads();
        for (int h = tid; h < HH; h += NTA) g_om23[bt*HH + h] = fdec(((unsigned*)(sm + A_OM))[h]);
    } else {
        for (int h = tid; h < HH; h += NTA) g_om23[bt*HH + h] = 0.f;
    }
}

// ---------------- Phase B smem float offsets ----------------
#define B_HST 0        // 24000  compact h store (160x150)
#define B_HM1 24000    // 12000  h_m1 (80x150)
#define B_GHB 36000    // 3600   gh for 8-hit group (8x450)
#define B_HPB 39600    // 1216   h_prev gather (8x152)
#define B_BHS 40816    // 464    bh
#define B_OUT 41280    // 2400   outs (16x150)
#define B_TMP 43680    // 512
#define B_VU  44192    // 16
#define B_SCR 44208    // 16
#define B_PL  44224    // 160 pooled
#define B_TOTF 44384
// shorts at byte 177536; ints at 180644; total ~180656 B

__global__ void __launch_bounds__(NTB, 1) phaseB(
    const int* __restrict__ lens,
    const float* __restrict__ bh,
    const float* __restrict__ Wd, const float* __restrict__ bd,
    const float* __restrict__ context,
    const float* __restrict__ Wc, const float* __restrict__ bc,
    float* __restrict__ out)
{
    extern __shared__ float sm[];
    short* map     = (short*)((char*)sm + B_TOTF*4);  // 1024
    short* rowsl   = map + 1024;      // 160
    short* m1L     = rowsl + 160;     // 80
    short* m23L    = m1L + 80;        // 80
    short* hitflag = m23L + 80;       // 80 (per m1 row: hit? )
    short* hitrow  = hitflag + 80;    // 64 (m1-row index of hit i)
    short* hitS    = hitrow + 64;     // 64 (HST slot of hit i)
    int* ints      = (int*)((char*)hitS + 64*2 + 4);  // aligned; [0]=nh [1]=nrows

    const int b = blockIdx.x, tid = threadIdx.x;
    const int lane = tid & 31, wid = tid >> 5;

    for (int i = tid; i < N_; i += NTB) map[i] = -1;
    for (int i = tid; i < G3; i += NTB) sm[B_BHS + i] = bh[i];
    if (tid == 0) ints[1] = 0;
    __syncthreads();

    for (int t = 0; t < T_; t++) {
        const int bt = b*T_ + t;
        const int c1 = g_c1[bt], c23 = g_c23[bt];
        for (int i = tid; i < c1;  i += NTB) m1L[i]  = g_m1i[bt*MAXM + i];
        for (int i = tid; i < c23; i += NTB) m23L[i] = g_m23i[bt*MAXM + i];
        __syncthreads();

        // ---- hit detection (warp-ballot, ordered) ----
        if (wid == 0) {
            int nh = 0;
            const unsigned lt = (1u << lane) - 1u;
            for (int base = 0; base < c1; base += 32) {
                int r = base + lane;
                short s = (r < c1) ? map[m1L[r]] : (short)-1;
                unsigned mk = __ballot_sync(0xffffffffu, s >= 0);
                if (s >= 0) {
                    int p = nh + __popc(mk & lt);
                    if (p < MAXHIT) { hitrow[p] = (short)r; hitS[p] = s; hitflag[r] = 1; }
                    else hitflag[r] = 0;
                } else if (r < c1) hitflag[r] = 0;
                nh += __popc(mk);
            }
            if (lane == 0) ints[0] = min(nh, MAXHIT);
        }
        __syncthreads();
        const int nh = ints[0];
        const float* giB = g_gi + (size_t)bt * MAXM * G3;

        // ---- non-hit GRU rows (h_prev = 0) ----
        for (int task = tid; task < c1*HH; task += NTB) {
            int r = task / HH, h = task - r*HH;
            if (!hitflag[r]) {
                const float* gir = giB + r*G3;
                float rr = 1.f / (1.f + __expf(-(gir[h]       + sm[B_BHS + h])));
                float zz = 1.f / (1.f + __expf(-(gir[150 + h] + sm[B_BHS + 150 + h])));
                float nn = tanhf(gir[300 + h] + rr * sm[B_BHS + 300 + h]);
                sm[B_HM1 + task] = (1.f - zz) * nn;
            }
        }

        // ---- hit groups of 8: gather h_prev, gh = h_prev @ Wh, gates ----
        for (int g0 = 0; g0 < nh; g0 += 8) {
            int nr = min(8, nh - g0);
            for (int task = tid; task < 8*152; task += NTB) {
                int g = task / 152, k = task - g*152;
                float v = 0.f;
                if (g < nr && k < HH) v = sm[B_HST + hitS[g0 + g]*HH + k];
                sm[B_HPB + task] = v;
            }
            __syncthreads();
            if (tid < G3) {
                float acc[8];
                #pragma unroll
                for (int g = 0; g < 8; g++) acc[g] = 0.f;
                const float4* wrow = (const float4*)(g_WhT + tid*152);
                #pragma unroll 2
                for (int k4 = 0; k4 < 38; k4++) {
                    float4 w = __ldg(wrow + k4);
                    #pragma unroll
                    for (int g = 0; g < 8; g++) {
                        float4 hp = *(const float4*)&sm[B_HPB + g*152 + k4*4];
                        acc[g] += w.x*hp.x + w.y*hp.y + w.z*hp.z + w.w*hp.w;
                    }
                }
                #pragma unroll
                for (int g = 0; g < 8; g++) sm[B_GHB + g*G3 + tid] = acc[g];
            }
            __syncthreads();
            for (int task = tid; task < nr*HH; task += NTB) {
                int g = task / HH, h = task - g*HH;
                int r = hitrow[g0 + g];
                const float* gir = giB + r*G3;
                const float* ghg = sm + B_GHB + g*G3;
                float hp = sm[B_HPB + g*152 + h];
                float rr = 1.f / (1.f + __expf(-(gir[h]       + sm[B_BHS + h]       + ghg[h])));
                float zz = 1.f / (1.f + __expf(-(gir[150 + h] + sm[B_BHS + 150 + h] + ghg[150 + h])));
                float nn = tanhf(gir[300 + h] + rr * (sm[B_BHS + 300 + h] + ghg[300 + h]));
                sm[B_HM1 + r*HH + h] = (1.f - zz) * nn + zz * hp;
            }
            __syncthreads();
        }
        __syncthreads();

        // ---- outs = gated om1 + om23 ----
        for (int h = tid; h < HH; h += NTB) {
            float mx = -1e30f;
            for (int r = 0; r < c1; r++) mx = fmaxf(mx, sm[B_HM1 + r*HH + h]);
            float o1 = (c1 > 0) ? mx : 0.f;
            sm[B_OUT + t*HH + h] = o1 + g_om23[bt*HH + h];
        }
        const int oldn = ints[1];
        for (int i = tid; i < oldn; i += NTB) map[rowsl[i]] = -1;
        __syncthreads();

        // ---- rebuild compact store ----
        const int newn = c1 + ((t > 0) ? c23 : 0);
        for (int task = tid; task < newn*HH; task += NTB) {
            int s = task / HH, h = task - s*HH;
            sm[B_HST + task] = (s < c1) ? sm[B_HM1 + s*HH + h]
                                        : g_h23[(bt*MAXM + (s - c1))*HH + h];
        }
        for (int i = tid; i < newn; i += NTB) {
            short m = (i < c1) ? m1L[i] : m23L[i - c1];
            rowsl[i] = m; map[m] = (short)i;
        }
        if (tid == 0) ints[1] = newn;
        __syncthreads();
    }

    // ---- visit attention ----
    for (int task = tid; task < T_*GS; task += NTB) {
        int tt = task >> 5, a = task & 31;
        float acc = __ldg(bd + a);
        const float* o = sm + B_OUT + tt*HH;
        for (int h = 0; h < HH; h++) acc += o[h] * __ldg(Wd + h*GS + a);
        sm[B_TMP + task] = acc;
    }
    __syncthreads();
    if (tid < T_) {
        float acc = 0.f;
        for (int a = 0; a < GS; a++) acc += sm[B_TMP + tid*GS + a] * __ldg(context + a);
        sm[B_VU + tid] = acc;
    }
    __syncthreads();
    if (tid < 32) {
        int L = lens[b];
        float v = (tid < T_ && tid < L) ? sm[B_VU + tid] : -1e30f;
        float mx = v;
        for (int o = 16; o; o >>= 1) mx = fmaxf(mx, __shfl_xor_sync(0xffffffffu, mx, o));
        float e = (tid < T_ && tid < L) ? __expf(v - mx) : 0.f;
        float s = e;
        for (int o = 16; o; o >>= 1) s += __shfl_xor_sync(0xffffffffu, s, o);
        if (tid < T_) sm[B_SCR + tid] = e / s;
    }
    __syncthreads();
    for (int h = tid; h < HH; h += NTB) {
        float acc = 0.f;
        for (int tt = 0; tt < T_; tt++) acc += sm[B_SCR + tt] * sm[B_OUT + tt*HH + h];
        sm[B_PL + h] = acc;
    }
    __syncthreads();

    // ---- classifier: 256 threads x 4 outputs, float4 Wc loads ----
    if (tid < 256) {
        int o4 = tid * 4;
        float4 acc = *(const float4*)(bc + o4);
        const float4* wc4 = (const float4*)Wc + tid;
        #pragma unroll 2
        for (int h = 0; h < HH; h++) {
            float p = sm[B_PL + h];
            float4 w = __ldg(wc4 + h * (ONUM/4));
            acc.x += p * w.x; acc.y += p * w.y; acc.z += p * w.z; acc.w += p * w.w;
        }
        float4 r;
        r.x = 1.f / (1.f + __expf(-acc.x));
        r.y = 1.f / (1.f + __expf(-acc.y));
        r.z = 1.f / (1.f + __expf(-acc.z));
        r.w = 1.f / (1.f + __expf(-acc.w));
        *(float4*)(out + b*ONUM + o4) = r;
    }
}

extern "C" void kernel_launch(void* const* d_in, const int* in_sizes, int n_in,
                              void* d_out, int out_size)
{
    const float* code_x    = (const float*)d_in[0];
    const float* divided   = (const float*)d_in[1];
    const float* neighbors = (const float*)d_in[2];
    const int*   lens      = (const int*)d_in[3];
    const float* adj       = (const float*)d_in[4];
    const float* c_emb     = (const float*)d_in[5];
    const float* n_emb     = (const float*)d_in[6];
    const float* u_emb     = (const float*)d_in[7];
    const float* Wg = (const float*)d_in[8];  const float* bg = (const float*)d_in[9];
    const float* Wi = (const float*)d_in[10]; const float* bi = (const float*)d_in[11];
    const float* Wh = (const float*)d_in[12]; const float* bh = (const float*)d_in[13];
    const float* Wq = (const float*)d_in[14]; const float* bq = (const float*)d_in[15];
    const float* Wk = (const float*)d_in[16]; const float* bk = (const float*)d_in[17];
    const float* Wv = (const float*)d_in[18]; const float* bv = (const float*)d_in[19];
    const float* Wd = (const float*)d_in[20]; const float* bd = (const float*)d_in[21];
    const float* context = (const float*)d_in[22];
    const float* Wc = (const float*)d_in[23]; const float* bc = (const float*)d_in[24];
    float* out = (float*)d_out;

    cudaFuncSetAttribute(phaseA, cudaFuncAttributeMaxDynamicSharedMemorySize, 210000);
    cudaFuncSetAttribute(phaseB, cudaFuncAttributeMaxDynamicSharedMemorySize, 181000);

    transWh<<<(G3*152 + 255)/256, 256>>>(Wh);
    phaseA<<<B_*T_, NTA, 210000>>>(code_x, divided, neighbors, adj, c_emb, n_emb, u_emb,
                                   Wg, bg, Wi, bi, Wq, bq, Wk, bk, Wv, bv);
    phaseB<<<B_, NTB, 181000>>>(lens, bh, Wd, bd, context, Wc, bc, out);
}

// round 5
// speedup vs baseline: 1.2263x; 1.1026x over previous
#include <cuda_runtime.h>
#include <math.h>
#include <stdint.h>

#define B_ 8
#define T_ 16
#define N_ 1024
#define CS 48
#define GS 32
#define HH 150
#define G3 450
#define ONUM 1024
#define MAXA 160
#define MAXM 80
#define NTA 256
#define NTB 512
#define MAXHIT 64

// ------------- device scratch (no cudaMalloc allowed) -------------
__device__ float g_gi[B_*T_*MAXM*G3];     // GRU input gates at m1 rows
__device__ float g_h23[B_*T_*MAXM*HH];    // attention hidden at m23 rows
__device__ float g_om23[B_*T_*HH];        // gated max-pool over m23 rows
__device__ int   g_c1[B_*T_];
__device__ int   g_c23[B_*T_];
__device__ short g_m1i[B_*T_*MAXM];
__device__ short g_m23i[B_*T_*MAXM];
__device__ float g_WhT[G3*152];           // Wh transposed [450][152], rows padded

__device__ __forceinline__ unsigned fenc(float f){
    unsigned u = __float_as_uint(f);
    return (u & 0x80000000u) ? ~u : (u | 0x80000000u);
}
__device__ __forceinline__ float fdec(unsigned u){
    return (u & 0x80000000u) ? __uint_as_float(u ^ 0x80000000u) : __uint_as_float(~u);
}

// ---------------- Phase A smem float offsets ----------------
#define AW_G 0        // 1536  Wg (48x32)
#define AW_Q 1536     // 1024  Wq
#define AW_K 2560     // 1024  Wk
#define AW_V 3584     // 4800  Wv (32x150)
#define AB_G 8384     // 32
#define AB_Q 8416     // 32
#define AB_K 8448     // 32
#define AB_V 8480     // 160 (150 used)
#define A_OM 8640     // 160 (unsigned encoded max)
#define A_EC 8800     // 15360  E_cur (320x48)
#define A_EP 24160    // 15360  E_prev
#define A_IN 39520    // 7680   in48 (160x48)
#define A_NP 47200    // 3840 + 480 pad  np (80x48)
#define A_TOTF 51520
// overlays (after stages retire)
#define A_CO 8800     // co 160x32
#define A_QR 13920    // qrows 80x32
#define A_Qb 24160    // q 80x32
#define A_Kb 26720    // k 80x32
#define A_Pb 29280    // P 80x80
#define A_Vb 39520    // v 80x150
// shorts at byte 206080 (2544 shorts), flags at 211168, cnts at 211248; total 211280 B
#define A_SMEM 211280

__global__ void __launch_bounds__(NTA) phaseA(
    const float* __restrict__ code_x, const float* __restrict__ divided,
    const float* __restrict__ neighbors, const float* __restrict__ adj,
    const float* __restrict__ c_emb, const float* __restrict__ n_emb,
    const float* __restrict__ u_emb,
    const float* __restrict__ Wg, const float* __restrict__ bg,
    const float* __restrict__ Wi, const float* __restrict__ bi,
    const float* __restrict__ Wq, const float* __restrict__ bq,
    const float* __restrict__ Wk, const float* __restrict__ bk,
    const float* __restrict__ Wv, const float* __restrict__ bv,
    const float* __restrict__ Wh)
{
    extern __shared__ float sm[];
    short* sh      = (short*)((char*)sm + A_TOTF*4);
    short* rowmap  = sh;              // 1024
    short* idxA    = sh + 1024;       // 160
    short* idxNb   = idxA + MAXA;
    short* idxAp   = idxNb + MAXA;
    short* idxNbp  = idxAp + MAXA;
    short* m1l     = idxNbp + MAXA;   // 80
    short* m23l    = m1l + MAXM;      // 80
    short* aiof1   = m23l + MAXM;     // 80
    short* lstC    = aiof1 + MAXM;    // 320
    short* lstP    = lstC + 2*MAXA;   // 320
    unsigned char* flags = (unsigned char*)sm + 211168; // 80
    int* cnts      = (int*)((char*)sm + 211248);        // 8

    const int bt = blockIdx.x;
    const int t = bt & 15;
    const int tid = threadIdx.x, lane = tid & 31, wid = tid >> 5;

    // ---- Wh transpose (disjoint slices across the 128 blocks) ----
    for (int i = bt*NTA + tid; i < G3*152; i += 128*NTA) {
        int j = i / 152, k = i - j*152;
        g_WhT[i] = (k < HH) ? Wh[k*G3 + j] : 0.f;
    }

    // ---- weights / biases into smem; init OM to encoded -inf ----
    for (int i = tid; i < CS*GS; i += NTA) sm[AW_G + i] = Wg[i];
    for (int i = tid; i < GS*GS; i += NTA) { sm[AW_Q + i] = Wq[i]; sm[AW_K + i] = Wk[i]; }
    for (int i = tid; i < GS*HH; i += NTA) sm[AW_V + i] = Wv[i];
    if (tid < GS) { sm[AB_G + tid] = bg[tid]; sm[AB_Q + tid] = bq[tid]; sm[AB_K + tid] = bk[tid]; }
    for (int i = tid; i < HH; i += NTA) sm[AB_V + i] = bv[i];
    {
        unsigned negenc = fenc(-1e30f);
        for (int i = tid; i < 160; i += NTA) ((unsigned*)(sm + A_OM))[i] = negenc;
    }

    // ---- ordered list building via warp ballots ----
    if (wid == 0) {
        int cAa = 0, cNbv = 0, cc1 = 0, cc23 = 0;
        const int base0 = bt * N_;
        const unsigned lt = (1u << lane) - 1u;
        for (int base = 0; base < N_; base += 32) {
            int n = base + lane;
            float cx  = code_x[base0 + n];
            float m1v = divided[(base0 + n)*3 + 0];
            float m2v = divided[(base0 + n)*3 + 1];
            float m3v = divided[(base0 + n)*3 + 2];
            float nbv = neighbors[base0 + n];
            unsigned mk = __ballot_sync(0xffffffffu, cx > 0.f);
            if (cx > 0.f) { int p = cAa + __popc(mk & lt); if (p < MAXA) { idxA[p] = (short)n; rowmap[n] = (short)p; } }
            cAa += __popc(mk);
            mk = __ballot_sync(0xffffffffu, nbv > 0.f);
            if (nbv > 0.f) { int p = cNbv + __popc(mk & lt); if (p < MAXA) idxNb[p] = (short)n; }
            cNbv += __popc(mk);
            mk = __ballot_sync(0xffffffffu, m1v > 0.f);
            if (m1v > 0.f) { int p = cc1 + __popc(mk & lt); if (p < MAXM) m1l[p] = (short)n; }
            cc1 += __popc(mk);
            bool e23 = (m2v > 0.f) || (m3v > 0.f);
            mk = __ballot_sync(0xffffffffu, e23);
            if (e23) { int p = cc23 + __popc(mk & lt); if (p < MAXM) { m23l[p] = (short)n; flags[p] = (m2v > 0.f) ? 1 : 0; } }
            cc23 += __popc(mk);
        }
        if (lane == 0) { cnts[0] = min(cAa, MAXA); cnts[1] = min(cNbv, MAXA);
                         cnts[4] = min(cc1, MAXM); cnts[5] = min(cc23, MAXM); }
    } else if (wid == 1) {
        if (t > 0) {
            int cAp = 0, cNbp = 0;
            const int base0 = (bt - 1) * N_;
            const unsigned lt = (1u << lane) - 1u;
            for (int base = 0; base < N_; base += 32) {
                int n = base + lane;
                float cx  = code_x[base0 + n];
                float nbv = neighbors[base0 + n];
                unsigned mk = __ballot_sync(0xffffffffu, cx > 0.f);
                if (cx > 0.f) { int p = cAp + __popc(mk & lt); if (p < MAXA) idxAp[p] = (short)n; }
                cAp += __popc(mk);
                mk = __ballot_sync(0xffffffffu, nbv > 0.f);
                if (nbv > 0.f) { int p = cNbp + __popc(mk & lt); if (p < MAXA) idxNbp[p] = (short)n; }
                cNbp += __popc(mk);
            }
            if (lane == 0) { cnts[2] = min(cAp, MAXA); cnts[3] = min(cNbp, MAXA); }
        } else if (lane == 0) { cnts[2] = 0; cnts[3] = 0; }
    }
    __syncthreads();

    const int cA = cnts[0], cNb = cnts[1], cAp = cnts[2], cNbp = cnts[3];
    const int c1 = cnts[4], c23 = cnts[5];
    const int totC = cA + cNb, totP = cAp + cNbp;

    if (tid == 0) { g_c1[bt] = c1; g_c23[bt] = c23; }
    for (int i = tid; i < c1;  i += NTA) g_m1i[bt*MAXM + i]  = m1l[i];
    for (int i = tid; i < c23; i += NTA) g_m23i[bt*MAXM + i] = m23l[i];
    if (t > 0)
        for (int i = tid; i < c23; i += NTA)
            if ((flags[i] & 1) && neighbors[(bt - 1)*N_ + m23l[i]] > 0.f) flags[i] |= 2;
    {
        int c1p = (c1 + 7) & ~7;
        for (int i = tid; i < c1p; i += NTA) aiof1[i] = (i < c1) ? rowmap[m1l[i]] : (short)0;
    }
    // combined index lists (enables batched prefetch in S1/S1b)
    for (int i = tid; i < totC; i += NTA) lstC[i] = (i < cA) ? idxA[i] : idxNb[i - cA];
    if (t > 0)
        for (int i = tid; i < totP; i += NTA) lstP[i] = (i < cAp) ? idxAp[i] : idxNbp[i - cAp];
    for (int task = tid; task < totC*CS; task += NTA) {
        int j = task / CS, c = task - j*CS;
        int n = (j < cA) ? idxA[j] : idxNb[j - cA];
        sm[A_EC + task] = (j < cA) ? c_emb[n*CS + c] : n_emb[n*CS + c];
    }
    if (t > 0)
        for (int task = tid; task < totP*CS; task += NTA) {
            int j = task / CS, c = task - j*CS;
            int n = (j < cAp) ? idxAp[j] : idxNbp[j - cAp];
            sm[A_EP + task] = (j < cAp) ? c_emb[n*CS + c] : n_emb[n*CS + c];
        }
    __syncthreads();

    // ---- S1: GraphLayer aggregation input at active rows (batch-8 prefetch) ----
    for (int task = tid; task < cA*4; task += NTA) {
        int ai = task >> 2, ch = (task & 3) * 12;
        const float* arow = adj + (size_t)idxA[ai] * N_;
        float acc[12];
        const float* e0 = sm + A_EC + ai*CS + ch;
        #pragma unroll
        for (int c = 0; c < 12; c++) acc[c] = e0[c];
        for (int j0 = 0; j0 < totC; j0 += 8) {
            float av[8];
            #pragma unroll
            for (int u = 0; u < 8; u++) {
                int j = j0 + u;
                av[u] = (j < totC) ? __ldg(arow + lstC[j]) : 0.f;
            }
            #pragma unroll
            for (int u = 0; u < 8; u++) {
                if (av[u] != 0.f) {
                    const float* er = sm + A_EC + (j0 + u)*CS + ch;
                    #pragma unroll
                    for (int c = 0; c < 12; c++) acc[c] += av[u] * er[c];
                }
            }
        }
        float* o = sm + A_IN + ai*CS + ch;
        #pragma unroll
        for (int c = 0; c < 12; c++) o[c] = acc[c];
    }
    // ---- S1b: no_{t-1} input at m2 rows (gated by prev neighbor mask) ----
    if (t > 0)
        for (int task = tid; task < c23*4; task += NTA) {
            int mi = task >> 2, ch = (task & 3) * 12;
            float acc[12];
            #pragma unroll
            for (int c = 0; c < 12; c++) acc[c] = 0.f;
            if (flags[mi] & 2) {
                int m = m23l[mi];
                const float* arow = adj + (size_t)m * N_;
                const float* nr = n_emb + m*CS + ch;
                #pragma unroll
                for (int c = 0; c < 12; c++) acc[c] = nr[c];
                for (int j0 = 0; j0 < totP; j0 += 8) {
                    float av[8];
                    #pragma unroll
                    for (int u = 0; u < 8; u++) {
                        int j = j0 + u;
                        av[u] = (j < totP) ? __ldg(arow + lstP[j]) : 0.f;
                    }
                    #pragma unroll
                    for (int u = 0; u < 8; u++) {
                        if (av[u] != 0.f) {
                            const float* er = sm + A_EP + (j0 + u)*CS + ch;
                            #pragma unroll
                            for (int c = 0; c < 12; c++) acc[c] += av[u] * er[c];
                        }
                    }
                }
            }
            float* o = sm + A_NP + mi*CS + ch;
            #pragma unroll
            for (int c = 0; c < 12; c++) o[c] = acc[c];
        }
    __syncthreads();

    // ---- S2: co = lrelu(in48 @ Wg + bg); qrows ----
    for (int task = tid; task < cA*GS; task += NTA) {
        int ai = task >> 5, g = task & 31;
        float acc = sm[AB_G + g];
        const float* in = sm + A_IN + ai*CS;
        #pragma unroll 8
        for (int c = 0; c < CS; c++) acc += in[c] * sm[AW_G + c*GS + g];
        sm[A_CO + task] = acc > 0.f ? acc : 0.01f * acc;
    }
    if (t > 0)
        for (int task = tid; task < c23*GS; task += NTA) {
            int mi = task >> 5, g = task & 31;
            float v;
            if (flags[mi] & 1) {
                float acc = sm[AB_G + g];
                const float* in = sm + A_NP + mi*CS;
                #pragma unroll 8
                for (int c = 0; c < CS; c++) acc += in[c] * sm[AW_G + c*GS + g];
                v = acc > 0.f ? acc : 0.01f * acc;
            } else {
                v = u_emb[m23l[mi]*GS + g];
            }
            sm[A_QR + task] = v;
        }
    __syncthreads();

    // ---- S3: gi (always), q/k/v (t>0) ----
    if (c1 > 0) {
        int ng = (c1 + 7) >> 3;
        for (int task = tid; task < G3*ng; task += NTA) {
            int j = task % G3, grp = task / G3, r0 = grp * 8;
            float acc[8];
            int ai[8];
            #pragma unroll
            for (int g = 0; g < 8; g++) { acc[g] = 0.f; ai[g] = aiof1[r0 + g]; }
            for (int c = 0; c < GS; c++) {
                float w = __ldg(Wi + c*G3 + j);
                #pragma unroll
                for (int g = 0; g < 8; g++) acc[g] += sm[A_CO + ai[g]*GS + c] * w;
            }
            float bij = __ldg(bi + j);
            int nr = min(8, c1 - r0);
            #pragma unroll
            for (int g = 0; g < 8; g++)
                if (g < nr) g_gi[(bt*MAXM + r0 + g)*G3 + j] = acc[g] + bij;
        }
    }
    if (t > 0 && c23 > 0) {
        for (int task = tid; task < c23*GS; task += NTA) {
            int i = task >> 5, a = task & 31;
            const float* qr = sm + A_QR + i*GS;
            int ai = rowmap[m23l[i]];
            const float* co = sm + A_CO + ai*GS;
            float accq = sm[AB_Q + a], acck = sm[AB_K + a];
            #pragma unroll
            for (int g = 0; g < GS; g++) {
                accq += qr[g] * sm[AW_Q + g*GS + a];
                acck += co[g] * sm[AW_K + g*GS + a];
            }
            sm[A_Qb + task] = accq;
            sm[A_Kb + task] = acck;
        }
        for (int task = tid; task < c23*HH; task += NTA) {
            int i = task / HH, h = task - i*HH;
            const float* qr = sm + A_QR + i*GS;
            float acc = sm[AB_V + h];
            #pragma unroll
            for (int g = 0; g < GS; g++) acc += qr[g] * sm[AW_V + g*HH + h];
            sm[A_Vb + i*HH + h] = acc;
        }
    }
    __syncthreads();

    // ---- S4: scores + softmax (warp per query) ----
    if (t > 0 && c23 > 0) {
        const float scale = 0.17677669529663687f;  // 1/sqrt(32)
        for (int i = wid; i < c23; i += 8) {
            const float* qi = sm + A_Qb + i*GS;
            float mx = -1e30f;
            for (int j = lane; j < c23; j += 32) {
                const float* kj = sm + A_Kb + j*GS;
                float s = 0.f;
                #pragma unroll
                for (int g = 0; g < GS; g++) s += qi[g] * kj[g];
                s *= scale;
                sm[A_Pb + i*MAXM + j] = s;
                mx = fmaxf(mx, s);
            }
            for (int o = 16; o; o >>= 1) mx = fmaxf(mx, __shfl_xor_sync(0xffffffffu, mx, o));
            float sum = 0.f;
            for (int j = lane; j < c23; j += 32) {
                float e = __expf(sm[A_Pb + i*MAXM + j] - mx);
                sm[A_Pb + i*MAXM + j] = e; sum += e;
            }
            for (int o = 16; o; o >>= 1) sum += __shfl_xor_sync(0xffffffffu, sum, o);
            float inv = 1.f / sum;
            for (int j = lane; j < c23; j += 32) sm[A_Pb + i*MAXM + j] *= inv;
        }
    }
    __syncthreads();

    // ---- S5: h_m23 + om23 ----
    if (t > 0 && c23 > 0) {
        unsigned* OM = (unsigned*)(sm + A_OM);
        for (int task = tid; task < c23*HH; task += NTA) {
            int i = task / HH, h = task - i*HH;
            float acc = 0.f;
            const float* pr = sm + A_Pb + i*MAXM;
            for (int j = 0; j < c23; j++) acc += pr[j] * sm[A_Vb + j*HH + h];
            float hv = tanhf(acc);
            g_h23[(bt*MAXM + i)*HH + h] = hv;
            atomicMax(OM + h, fenc(hv));
        }
        __syncthreads();
        for (int h = tid; h < HH; h += NTA) g_om23[bt*HH + h] = fdec(((unsigned*)(sm + A_OM))[h]);
    } else {
        for (int h = tid; h < HH; h += NTA) g_om23[bt*HH + h] = 0.f;
    }
}

// ---------------- Phase B smem float offsets ----------------
#define B_HST 0        // 24000  compact h store (160x150)
#define B_HM1 24000    // 12000  h_m1 (80x150)
#define B_GHB 36000    // 3600   gh group (8x450)
#define B_HPB 39600    // 1216   h_prev gather (8x152)
#define B_BHS 40816    // 464    bh
#define B_OUT 41280    // 2400   outs (16x150)
#define B_TMP 43680    // 512
#define B_VU  44192    // 16
#define B_SCR 44208    // 16
#define B_PL  44224    // 160 pooled
#define B_TOTF 44384

// gh = h_prev @ Wh for NR rows; only the actual hit count worth of FMAs
template<int NR>
__device__ __forceinline__ void gh_mm(float* sm, int tid) {
    if (tid < G3) {
        float acc[NR];
        #pragma unroll
        for (int g = 0; g < NR; g++) acc[g] = 0.f;
        const float4* wrow = (const float4*)(g_WhT + tid*152);
        #pragma unroll 2
        for (int k4 = 0; k4 < 38; k4++) {
            float4 w = __ldg(wrow + k4);
            #pragma unroll
            for (int g = 0; g < NR; g++) {
                float4 hp = *(const float4*)&sm[B_HPB + g*152 + k4*4];
                acc[g] += w.x*hp.x + w.y*hp.y + w.z*hp.z + w.w*hp.w;
            }
        }
        #pragma unroll
        for (int g = 0; g < NR; g++) sm[B_GHB + g*G3 + tid] = acc[g];
    }
}

__global__ void __launch_bounds__(NTB, 1) phaseB(
    const int* __restrict__ lens,
    const float* __restrict__ bh,
    const float* __restrict__ Wd, const float* __restrict__ bd,
    const float* __restrict__ context,
    const float* __restrict__ Wc, const float* __restrict__ bc,
    float* __restrict__ out)
{
    extern __shared__ float sm[];
    short* map     = (short*)((char*)sm + B_TOTF*4);  // 1024
    short* rowsl   = map + 1024;      // 160
    short* m1L     = rowsl + 160;     // 80
    short* m23L    = m1L + 80;        // 80
    short* hitflag = m23L + 80;       // 80
    short* hitrow  = hitflag + 80;    // 64
    short* hitS    = hitrow + 64;     // 64
    int* ints      = (int*)((char*)hitS + 64*2 + 4);  // [0]=nh [1]=nrows

    const int b = blockIdx.x, tid = threadIdx.x;
    const int lane = tid & 31, wid = tid >> 5;

    for (int i = tid; i < N_; i += NTB) map[i] = -1;
    for (int i = tid; i < G3; i += NTB) sm[B_BHS + i] = bh[i];
    if (tid == 0) ints[1] = 0;
    __syncthreads();

    for (int t = 0; t < T_; t++) {
        const int bt = b*T_ + t;
        const int c1 = g_c1[bt], c23 = g_c23[bt];
        for (int i = tid; i < c1;  i += NTB) m1L[i]  = g_m1i[bt*MAXM + i];
        for (int i = tid; i < c23; i += NTB) m23L[i] = g_m23i[bt*MAXM + i];
        __syncthreads();

        // ---- hit detection (warp-ballot, ordered) ----
        if (wid == 0) {
            int nh = 0;
            const unsigned lt = (1u << lane) - 1u;
            for (int base = 0; base < c1; base += 32) {
                int r = base + lane;
                short s = (r < c1) ? map[m1L[r]] : (short)-1;
                unsigned mk = __ballot_sync(0xffffffffu, s >= 0);
                if (s >= 0) {
                    int p = nh + __popc(mk & lt);
                    if (p < MAXHIT) { hitrow[p] = (short)r; hitS[p] = s; hitflag[r] = 1; }
                    else hitflag[r] = 0;
                } else if (r < c1) hitflag[r] = 0;
                nh += __popc(mk);
            }
            if (lane == 0) ints[0] = min(nh, MAXHIT);
        }
        __syncthreads();
        const int nh = ints[0];
        const float* giB = g_gi + (size_t)bt * MAXM * G3;

        // ---- non-hit GRU rows (h_prev = 0) ----
        for (int task = tid; task < c1*HH; task += NTB) {
            int r = task / HH, h = task - r*HH;
            if (!hitflag[r]) {
                const float* gir = giB + r*G3;
                float rr = 1.f / (1.f + __expf(-(gir[h]       + sm[B_BHS + h])));
                float zz = 1.f / (1.f + __expf(-(gir[150 + h] + sm[B_BHS + 150 + h])));
                float nn = tanhf(gir[300 + h] + rr * sm[B_BHS + 300 + h]);
                sm[B_HM1 + task] = (1.f - zz) * nn;
            }
        }

        // ---- hit groups (size-adaptive): gather, gh = h_prev @ Wh, gates ----
        for (int g0 = 0; g0 < nh; g0 += 8) {
            int nr = min(8, nh - g0);
            int path = (nr > 4) ? 8 : nr;   // 1,2,3,4 or 8
            for (int task = tid; task < path*152; task += NTB) {
                int g = task / 152, k = task - g*152;
                float v = 0.f;
                if (g < nr && k < HH) v = sm[B_HST + hitS[g0 + g]*HH + k];
                sm[B_HPB + task] = v;
            }
            __syncthreads();
            switch (path) {
                case 1: gh_mm<1>(sm, tid); break;
                case 2: gh_mm<2>(sm, tid); break;
                case 3: gh_mm<3>(sm, tid); break;
                case 4: gh_mm<4>(sm, tid); break;
                default: gh_mm<8>(sm, tid); break;
            }
            __syncthreads();
            for (int task = tid; task < nr*HH; task += NTB) {
                int g = task / HH, h = task - g*HH;
                int r = hitrow[g0 + g];
                const float* gir = giB + r*G3;
                const float* ghg = sm + B_GHB + g*G3;
                float hp = sm[B_HPB + g*152 + h];
                float rr = 1.f / (1.f + __expf(-(gir[h]       + sm[B_BHS + h]       + ghg[h])));
                float zz = 1.f / (1.f + __expf(-(gir[150 + h] + sm[B_BHS + 150 + h] + ghg[150 + h])));
                float nn = tanhf(gir[300 + h] + rr * (sm[B_BHS + 300 + h] + ghg[300 + h]));
                sm[B_HM1 + r*HH + h] = (1.f - zz) * nn + zz * hp;
            }
            __syncthreads();
        }
        __syncthreads();

        // ---- outs = gated om1 + om23 ----
        for (int h = tid; h < HH; h += NTB) {
            float mx = -1e30f;
            for (int r = 0; r < c1; r++) mx = fmaxf(mx, sm[B_HM1 + r*HH + h]);
            float o1 = (c1 > 0) ? mx : 0.f;
            sm[B_OUT + t*HH + h] = o1 + g_om23[bt*HH + h];
        }
        const int oldn = ints[1];
        for (int i = tid; i < oldn; i += NTB) map[rowsl[i]] = -1;
        __syncthreads();

        // ---- rebuild compact store ----
        const int newn = c1 + ((t > 0) ? c23 : 0);
        for (int task = tid; task < newn*HH; task += NTB) {
            int s = task / HH, h = task - s*HH;
            sm[B_HST + task] = (s < c1) ? sm[B_HM1 + s*HH + h]
                                        : g_h23[(bt*MAXM + (s - c1))*HH + h];
        }
        for (int i = tid; i < newn; i += NTB) {
            short m = (i < c1) ? m1L[i] : m23L[i - c1];
            rowsl[i] = m; map[m] = (short)i;
        }
        if (tid == 0) ints[1] = newn;
        __syncthreads();
    }

    // ---- visit attention ----
    for (int task = tid; task < T_*GS; task += NTB) {
        int tt = task >> 5, a = task & 31;
        float acc = __ldg(bd + a);
        const float* o = sm + B_OUT + tt*HH;
        for (int h = 0; h < HH; h++) acc += o[h] * __ldg(Wd + h*GS + a);
        sm[B_TMP + task] = acc;
    }
    __syncthreads();
    if (tid < T_) {
        float acc = 0.f;
        for (int a = 0; a < GS; a++) acc += sm[B_TMP + tid*GS + a] * __ldg(context + a);
        sm[B_VU + tid] = acc;
    }
    __syncthreads();
    if (tid < 32) {
        int L = lens[b];
        float v = (tid < T_ && tid < L) ? sm[B_VU + tid] : -1e30f;
        float mx = v;
        for (int o = 16; o; o >>= 1) mx = fmaxf(mx, __shfl_xor_sync(0xffffffffu, mx, o));
        float e = (tid < T_ && tid < L) ? __expf(v - mx) : 0.f;
        float s = e;
        for (int o = 16; o; o >>= 1) s += __shfl_xor_sync(0xffffffffu, s, o);
        if (tid < T_) sm[B_SCR + tid] = e / s;
    }
    __syncthreads();
    for (int h = tid; h < HH; h += NTB) {
        float acc = 0.f;
        for (int tt = 0; tt < T_; tt++) acc += sm[B_SCR + tt] * sm[B_OUT + tt*HH + h];
        sm[B_PL + h] = acc;
    }
    __syncthreads();

    // ---- classifier: 256 threads x 4 outputs, float4 Wc loads ----
    if (tid < 256) {
        int o4 = tid * 4;
        float4 acc = *(const float4*)(bc + o4);
        const float4* wc4 = (const float4*)Wc + tid;
        #pragma unroll 2
        for (int h = 0; h < HH; h++) {
            float p = sm[B_PL + h];
            float4 w = __ldg(wc4 + h * (ONUM/4));
            acc.x += p * w.x; acc.y += p * w.y; acc.z += p * w.z; acc.w += p * w.w;
        }
        float4 r;
        r.x = 1.f / (1.f + __expf(-acc.x));
        r.y = 1.f / (1.f + __expf(-acc.y));
        r.z = 1.f / (1.f + __expf(-acc.z));
        r.w = 1.f / (1.f + __expf(-acc.w));
        *(float4*)(out + b*ONUM + o4) = r;
    }
}

extern "C" void kernel_launch(void* const* d_in, const int* in_sizes, int n_in,
                              void* d_out, int out_size)
{
    const float* code_x    = (const float*)d_in[0];
    const float* divided   = (const float*)d_in[1];
    const float* neighbors = (const float*)d_in[2];
    const int*   lens      = (const int*)d_in[3];
    const float* adj       = (const float*)d_in[4];
    const float* c_emb     = (const float*)d_in[5];
    const float* n_emb     = (const float*)d_in[6];
    const float* u_emb     = (const float*)d_in[7];
    const float* Wg = (const float*)d_in[8];  const float* bg = (const float*)d_in[9];
    const float* Wi = (const float*)d_in[10]; const float* bi = (const float*)d_in[11];
    const float* Wh = (const float*)d_in[12]; const float* bh = (const float*)d_in[13];
    const float* Wq = (const float*)d_in[14]; const float* bq = (const float*)d_in[15];
    const float* Wk = (const float*)d_in[16]; const float* bk = (const float*)d_in[17];
    const float* Wv = (const float*)d_in[18]; const float* bv = (const float*)d_in[19];
    const float* Wd = (const float*)d_in[20]; const float* bd = (const float*)d_in[21];
    const float* context = (const float*)d_in[22];
    const float* Wc = (const float*)d_in[23]; const float* bc = (const float*)d_in[24];
    float* out = (float*)d_out;

    cudaFuncSetAttribute(phaseA, cudaFuncAttributeMaxDynamicSharedMemorySize, A_SMEM);
    cudaFuncSetAttribute(phaseB, cudaFuncAttributeMaxDynamicSharedMemorySize, 181000);

    phaseA<<<B_*T_, NTA, A_SMEM>>>(code_x, divided, neighbors, adj, c_emb, n_emb, u_emb,
                                   Wg, bg, Wi, bi, Wq, bq, Wk, bk, Wv, bv, Wh);
    phaseB<<<B_, NTB, 181000>>>(lens, bh, Wd, bd, context, Wc, bc, out);
}

// round 6
// speedup vs baseline: 1.8666x; 1.5222x over previous
#include <cuda_runtime.h>
#include <math.h>
#include <stdint.h>

#define B_ 8
#define T_ 16
#define N_ 1024
#define CS 48
#define GS 32
#define HH 150
#define G3 450
#define ONUM 1024
#define MAXA 160
#define MAXM 80
#define NTA 256
#define NTB 512

// ------------- device scratch (no cudaMalloc allowed) -------------
__device__ float g_gi[B_*T_*MAXM*G3];      // GRU input gates at m1 rows
__device__ float g_h23[B_*T_*MAXM*HH];     // attention hidden at m23 rows
__device__ float g_om23[B_*T_*HH];         // gated max-pool over m23 rows
__device__ float g_hm1[B_*T_*MAXM*HH];     // h_m1 rows (phaseA nonhit, phaseB hit)
__device__ float g_om1nh[B_*T_*152];       // max over NON-hit m1 rows (-1e30 if none)
__device__ int   g_c1[B_*T_];
__device__ int   g_nhit[B_*T_];
__device__ int   g_hmeta[B_*T_*MAXM];      // r | (srcpos<<8) | (is23<<16)
__device__ float g_WhT[G3*152];            // Wh transposed [450][152], rows padded

__device__ __forceinline__ unsigned fenc(float f){
    unsigned u = __float_as_uint(f);
    return (u & 0x80000000u) ? ~u : (u | 0x80000000u);
}
__device__ __forceinline__ float fdec(unsigned u){
    return (u & 0x80000000u) ? __uint_as_float(u ^ 0x80000000u) : __uint_as_float(~u);
}

// ---------------- Phase A smem float offsets ----------------
#define AW_G 0        // 1536  Wg (48x32)
#define AW_Q 1536     // 1024  Wq
#define AW_K 2560     // 1024  Wk
#define AW_V 3584     // 4800  Wv (32x150)
#define AB_G 8384     // 32
#define AB_Q 8416     // 32
#define AB_K 8448     // 32
#define AB_V 8480     // 160 (150 used)
#define A_OM 8640     // 160 (unsigned encoded max, om23)
#define A_EC 8800     // 15360  E_cur (320x48)
#define A_EP 24160    // 15360  E_prev
#define A_IN 39520    // 7680   in48 (160x48)
#define A_NP 47200    // 3840 + 480 pad  np (80x48)
// overlays (after stages retire)
#define A_CO 8800     // co 160x32
#define A_QR 13920    // qrows 80x32
#define A_Qb 24160    // q 80x32
#define A_Kb 26720    // k 80x32
#define A_Pb 29280    // P 80x80
#define A_Vb 39520    // v 80x150
#define A_OM1 51520   // 152 (unsigned encoded max, om1 nonhit)
#define A_BH  51672   // 456 (bh)
#define A_TOTF 52128  // floats end -> byte 208512
// shorts base 208512: rowmap 1024, idxA/Nb/Ap/Nbp 4*160, m1l/m23l/aiof1 3*80,
//                     lstC/lstP 2*320, prevmap 1024  = 3568 shorts -> ends 215648
// uchar flags 80 + hitA 80 -> 215808 ; cnts (8 int) at 215808 -> 215840
#define A_SMEM 215840

__global__ void __launch_bounds__(NTA) phaseA(
    const float* __restrict__ code_x, const float* __restrict__ divided,
    const float* __restrict__ neighbors, const float* __restrict__ adj,
    const float* __restrict__ c_emb, const float* __restrict__ n_emb,
    const float* __restrict__ u_emb,
    const float* __restrict__ Wg, const float* __restrict__ bg,
    const float* __restrict__ Wi, const float* __restrict__ bi,
    const float* __restrict__ Wq, const float* __restrict__ bq,
    const float* __restrict__ Wk, const float* __restrict__ bk,
    const float* __restrict__ Wv, const float* __restrict__ bv,
    const float* __restrict__ Wh, const float* __restrict__ bh)
{
    extern __shared__ float sm[];
    short* sh      = (short*)((char*)sm + A_TOTF*4);
    short* rowmap  = sh;              // 1024
    short* idxA    = sh + 1024;       // 160
    short* idxNb   = idxA + MAXA;
    short* idxAp   = idxNb + MAXA;
    short* idxNbp  = idxAp + MAXA;
    short* m1l     = idxNbp + MAXA;   // 80
    short* m23l    = m1l + MAXM;      // 80
    short* aiof1   = m23l + MAXM;     // 80
    short* lstC    = aiof1 + MAXM;    // 320
    short* lstP    = lstC + 2*MAXA;   // 320
    short* prevmap = lstP + 2*MAXA;   // 1024
    unsigned char* flags = (unsigned char*)sm + 215648; // 80
    unsigned char* hitA  = flags + 80;                  // 80
    int* cnts      = (int*)((char*)sm + 215808);        // 8

    const int bt = blockIdx.x;
    const int t = bt & 15;
    const int tid = threadIdx.x, lane = tid & 31, wid = tid >> 5;

    // ===== region 0: init =====
    for (int i = bt*NTA + tid; i < G3*152; i += 128*NTA) {   // Wh transpose slices
        int j = i / 152, k = i - j*152;
        g_WhT[i] = (k < HH) ? Wh[k*G3 + j] : 0.f;
    }
    for (int i = tid; i < CS*GS; i += NTA) sm[AW_G + i] = Wg[i];
    for (int i = tid; i < GS*GS; i += NTA) { sm[AW_Q + i] = Wq[i]; sm[AW_K + i] = Wk[i]; }
    for (int i = tid; i < GS*HH; i += NTA) sm[AW_V + i] = Wv[i];
    if (tid < GS) { sm[AB_G + tid] = bg[tid]; sm[AB_Q + tid] = bq[tid]; sm[AB_K + tid] = bk[tid]; }
    for (int i = tid; i < HH; i += NTA) sm[AB_V + i] = bv[i];
    for (int i = tid; i < G3; i += NTA) sm[A_BH + i] = bh[i];
    {
        unsigned negenc = fenc(-1e30f);
        for (int i = tid; i < 160; i += NTA) ((unsigned*)(sm + A_OM))[i] = negenc;
        for (int i = tid; i < 152; i += NTA) ((unsigned*)(sm + A_OM1))[i] = negenc;
    }
    for (int i = tid; i < N_; i += NTA) prevmap[i] = -1;
    __syncthreads();

    // ===== region 1: ballots =====
    if (wid == 0) {
        int cAa = 0, cNbv = 0, cc1 = 0, cc23 = 0;
        const int base0 = bt * N_;
        const unsigned lt = (1u << lane) - 1u;
        for (int base = 0; base < N_; base += 32) {
            int n = base + lane;
            float cx  = code_x[base0 + n];
            float m1v = divided[(base0 + n)*3 + 0];
            float m2v = divided[(base0 + n)*3 + 1];
            float m3v = divided[(base0 + n)*3 + 2];
            float nbv = neighbors[base0 + n];
            unsigned mk = __ballot_sync(0xffffffffu, cx > 0.f);
            if (cx > 0.f) { int p = cAa + __popc(mk & lt); if (p < MAXA) { idxA[p] = (short)n; rowmap[n] = (short)p; } }
            cAa += __popc(mk);
            mk = __ballot_sync(0xffffffffu, nbv > 0.f);
            if (nbv > 0.f) { int p = cNbv + __popc(mk & lt); if (p < MAXA) idxNb[p] = (short)n; }
            cNbv += __popc(mk);
            mk = __ballot_sync(0xffffffffu, m1v > 0.f);
            if (m1v > 0.f) { int p = cc1 + __popc(mk & lt); if (p < MAXM) m1l[p] = (short)n; }
            cc1 += __popc(mk);
            bool e23 = (m2v > 0.f) || (m3v > 0.f);
            mk = __ballot_sync(0xffffffffu, e23);
            if (e23) { int p = cc23 + __popc(mk & lt); if (p < MAXM) { m23l[p] = (short)n; flags[p] = (m2v > 0.f) ? 1 : 0; } }
            cc23 += __popc(mk);
        }
        if (lane == 0) { cnts[0] = min(cAa, MAXA); cnts[1] = min(cNbv, MAXA);
                         cnts[4] = min(cc1, MAXM); cnts[5] = min(cc23, MAXM); }
    } else if (wid == 1) {
        if (t > 0) {
            int cAp = 0, cNbp = 0;
            const int base0 = (bt - 1) * N_;
            const unsigned lt = (1u << lane) - 1u;
            for (int base = 0; base < N_; base += 32) {
                int n = base + lane;
                float cx  = code_x[base0 + n];
                float nbv = neighbors[base0 + n];
                unsigned mk = __ballot_sync(0xffffffffu, cx > 0.f);
                if (cx > 0.f) { int p = cAp + __popc(mk & lt); if (p < MAXA) idxAp[p] = (short)n; }
                cAp += __popc(mk);
                mk = __ballot_sync(0xffffffffu, nbv > 0.f);
                if (nbv > 0.f) { int p = cNbp + __popc(mk & lt); if (p < MAXA) idxNbp[p] = (short)n; }
                cNbp += __popc(mk);
            }
            if (lane == 0) { cnts[2] = min(cAp, MAXA); cnts[3] = min(cNbp, MAXA); }
        } else if (lane == 0) { cnts[2] = 0; cnts[3] = 0; }
    } else if (wid == 2 && t > 0) {
        // prevmap: prev-step m1 positions; prev-step m23 positions (eligible only t>=2)
        int p1 = 0, p23 = 0;
        const int base0 = (bt - 1) * N_;
        const unsigned lt = (1u << lane) - 1u;
        for (int base = 0; base < N_; base += 32) {
            int n = base + lane;
            float m1v = divided[(base0 + n)*3 + 0];
            float m2v = divided[(base0 + n)*3 + 1];
            float m3v = divided[(base0 + n)*3 + 2];
            bool b1 = m1v > 0.f;
            bool b23 = (m2v > 0.f) || (m3v > 0.f);
            unsigned mk = __ballot_sync(0xffffffffu, b1);
            if (b1) { int p = p1 + __popc(mk & lt); if (p < MAXM) prevmap[n] = (short)p; }
            p1 += __popc(mk);
            mk = __ballot_sync(0xffffffffu, b23);
            if (b23) { int p = p23 + __popc(mk & lt); if (p < MAXM && t >= 2) prevmap[n] = (short)(p | 0x4000); }
            p23 += __popc(mk);
        }
    }
    __syncthreads();

    const int cA = cnts[0], cNb = cnts[1], cAp = cnts[2], cNbp = cnts[3];
    const int c1 = cnts[4], c23 = cnts[5];
    const int totC = cA + cNb, totP = cAp + cNbp;

    // ===== region 2: hit compaction (warp 0), staging =====
    if (wid == 0) {
        int nhits = 0;
        const unsigned lt = (1u << lane) - 1u;
        for (int base = 0; base < c1; base += 32) {
            int r = base + lane;
            short pm = (r < c1) ? prevmap[m1l[r]] : (short)-1;
            bool hit = pm >= 0;
            unsigned mk = __ballot_sync(0xffffffffu, hit);
            if (r < c1) {
                if (hit) {
                    int p = nhits + __popc(mk & lt);
                    int srcpos = pm & 0x3FFF;
                    int is23   = (pm >> 14) & 1;
                    g_hmeta[bt*MAXM + p] = r | (srcpos << 8) | (is23 << 16);
                    hitA[r] = 1;
                } else hitA[r] = 0;
            }
            nhits += __popc(mk);
        }
        if (lane == 0) { g_nhit[bt] = nhits; g_c1[bt] = c1; }
    }
    if (t > 0)
        for (int i = tid; i < c23; i += NTA)
            if ((flags[i] & 1) && neighbors[(bt - 1)*N_ + m23l[i]] > 0.f) flags[i] |= 2;
    {
        int c1p = (c1 + 7) & ~7;
        for (int i = tid; i < c1p; i += NTA) aiof1[i] = (i < c1) ? rowmap[m1l[i]] : (short)0;
    }
    for (int i = tid; i < totC; i += NTA) lstC[i] = (i < cA) ? idxA[i] : idxNb[i - cA];
    if (t > 0)
        for (int i = tid; i < totP; i += NTA) lstP[i] = (i < cAp) ? idxAp[i] : idxNbp[i - cAp];
    for (int task = tid; task < totC*CS; task += NTA) {
        int j = task / CS, c = task - j*CS;
        int n = (j < cA) ? idxA[j] : idxNb[j - cA];
        sm[A_EC + task] = (j < cA) ? c_emb[n*CS + c] : n_emb[n*CS + c];
    }
    if (t > 0)
        for (int task = tid; task < totP*CS; task += NTA) {
            int j = task / CS, c = task - j*CS;
            int n = (j < cAp) ? idxAp[j] : idxNbp[j - cAp];
            sm[A_EP + task] = (j < cAp) ? c_emb[n*CS + c] : n_emb[n*CS + c];
        }
    __syncthreads();

    // ---- S1: GraphLayer aggregation input at active rows (batch-8 prefetch) ----
    for (int task = tid; task < cA*4; task += NTA) {
        int ai = task >> 2, ch = (task & 3) * 12;
        const float* arow = adj + (size_t)idxA[ai] * N_;
        float acc[12];
        const float* e0 = sm + A_EC + ai*CS + ch;
        #pragma unroll
        for (int c = 0; c < 12; c++) acc[c] = e0[c];
        for (int j0 = 0; j0 < totC; j0 += 8) {
            float av[8];
            #pragma unroll
            for (int u = 0; u < 8; u++) {
                int j = j0 + u;
                av[u] = (j < totC) ? __ldg(arow + lstC[j]) : 0.f;
            }
            #pragma unroll
            for (int u = 0; u < 8; u++) {
                if (av[u] != 0.f) {
                    const float* er = sm + A_EC + (j0 + u)*CS + ch;
                    #pragma unroll
                    for (int c = 0; c < 12; c++) acc[c] += av[u] * er[c];
                }
            }
        }
        float* o = sm + A_IN + ai*CS + ch;
        #pragma unroll
        for (int c = 0; c < 12; c++) o[c] = acc[c];
    }
    // ---- S1b: no_{t-1} input at m2 rows ----
    if (t > 0)
        for (int task = tid; task < c23*4; task += NTA) {
            int mi = task >> 2, ch = (task & 3) * 12;
            float acc[12];
            #pragma unroll
            for (int c = 0; c < 12; c++) acc[c] = 0.f;
            if (flags[mi] & 2) {
                int m = m23l[mi];
                const float* arow = adj + (size_t)m * N_;
                const float* nr = n_emb + m*CS + ch;
                #pragma unroll
                for (int c = 0; c < 12; c++) acc[c] = nr[c];
                for (int j0 = 0; j0 < totP; j0 += 8) {
                    float av[8];
                    #pragma unroll
                    for (int u = 0; u < 8; u++) {
                        int j = j0 + u;
                        av[u] = (j < totP) ? __ldg(arow + lstP[j]) : 0.f;
                    }
                    #pragma unroll
                    for (int u = 0; u < 8; u++) {
                        if (av[u] != 0.f) {
                            const float* er = sm + A_EP + (j0 + u)*CS + ch;
                            #pragma unroll
                            for (int c = 0; c < 12; c++) acc[c] += av[u] * er[c];
                        }
                    }
                }
            }
            float* o = sm + A_NP + mi*CS + ch;
            #pragma unroll
            for (int c = 0; c < 12; c++) o[c] = acc[c];
        }
    __syncthreads();

    // ---- S2: co = lrelu(in48 @ Wg + bg); qrows ----
    for (int task = tid; task < cA*GS; task += NTA) {
        int ai = task >> 5, g = task & 31;
        float acc = sm[AB_G + g];
        const float* in = sm + A_IN + ai*CS;
        #pragma unroll 8
        for (int c = 0; c < CS; c++) acc += in[c] * sm[AW_G + c*GS + g];
        sm[A_CO + task] = acc > 0.f ? acc : 0.01f * acc;
    }
    if (t > 0)
        for (int task = tid; task < c23*GS; task += NTA) {
            int mi = task >> 5, g = task & 31;
            float v;
            if (flags[mi] & 1) {
                float acc = sm[AB_G + g];
                const float* in = sm + A_NP + mi*CS;
                #pragma unroll 8
                for (int c = 0; c < CS; c++) acc += in[c] * sm[AW_G + c*GS + g];
                v = acc > 0.f ? acc : 0.01f * acc;
            } else {
                v = u_emb[m23l[mi]*GS + g];
            }
            sm[A_QR + task] = v;
        }
    __syncthreads();

    // ---- S3: gi at m1 rows; q/k/v (t>0) ----
    if (c1 > 0) {
        int ng = (c1 + 7) >> 3;
        for (int task = tid; task < G3*ng; task += NTA) {
            int j = task % G3, grp = task / G3, r0 = grp * 8;
            float acc[8];
            int ai[8];
            #pragma unroll
            for (int g = 0; g < 8; g++) { acc[g] = 0.f; ai[g] = aiof1[r0 + g]; }
            for (int c = 0; c < GS; c++) {
                float w = __ldg(Wi + c*G3 + j);
                #pragma unroll
                for (int g = 0; g < 8; g++) acc[g] += sm[A_CO + ai[g]*GS + c] * w;
            }
            float bij = __ldg(bi + j);
            int nr = min(8, c1 - r0);
            #pragma unroll
            for (int g = 0; g < 8; g++)
                if (g < nr) g_gi[((size_t)bt*MAXM + r0 + g)*G3 + j] = acc[g] + bij;
        }
    }
    if (t > 0 && c23 > 0) {
        for (int task = tid; task < c23*GS; task += NTA) {
            int i = task >> 5, a = task & 31;
            const float* qr = sm + A_QR + i*GS;
            int ai = rowmap[m23l[i]];
            const float* co = sm + A_CO + ai*GS;
            float accq = sm[AB_Q + a], acck = sm[AB_K + a];
            #pragma unroll
            for (int g = 0; g < GS; g++) {
                accq += qr[g] * sm[AW_Q + g*GS + a];
                acck += co[g] * sm[AW_K + g*GS + a];
            }
            sm[A_Qb + task] = accq;
            sm[A_Kb + task] = acck;
        }
        for (int task = tid; task < c23*HH; task += NTA) {
            int i = task / HH, h = task - i*HH;
            const float* qr = sm + A_QR + i*GS;
            float acc = sm[AB_V + h];
            #pragma unroll
            for (int g = 0; g < GS; g++) acc += qr[g] * sm[AW_V + g*HH + h];
            sm[A_Vb + i*HH + h] = acc;
        }
    }
    __syncthreads();

    // ---- S4: scores + softmax (warp per query) ----
    if (t > 0 && c23 > 0) {
        const float scale = 0.17677669529663687f;  // 1/sqrt(32)
        for (int i = wid; i < c23; i += 8) {
            const float* qi = sm + A_Qb + i*GS;
            float mx = -1e30f;
            for (int j = lane; j < c23; j += 32) {
                const float* kj = sm + A_Kb + j*GS;
                float s = 0.f;
                #pragma unroll
                for (int g = 0; g < GS; g++) s += qi[g] * kj[g];
                s *= scale;
                sm[A_Pb + i*MAXM + j] = s;
                mx = fmaxf(mx, s);
            }
            for (int o = 16; o; o >>= 1) mx = fmaxf(mx, __shfl_xor_sync(0xffffffffu, mx, o));
            float sum = 0.f;
            for (int j = lane; j < c23; j += 32) {
                float e = __expf(sm[A_Pb + i*MAXM + j] - mx);
                sm[A_Pb + i*MAXM + j] = e; sum += e;
            }
            for (int o = 16; o; o >>= 1) sum += __shfl_xor_sync(0xffffffffu, sum, o);
            float inv = 1.f / sum;
            for (int j = lane; j < c23; j += 32) sm[A_Pb + i*MAXM + j] *= inv;
        }
    }
    __syncthreads();

    // ---- S5: h_m23 + om23 ----
    if (t > 0 && c23 > 0) {
        unsigned* OM = (unsigned*)(sm + A_OM);
        for (int task = tid; task < c23*HH; task += NTA) {
            int i = task / HH, h = task - i*HH;
            float acc = 0.f;
            const float* pr = sm + A_Pb + i*MAXM;
            for (int j = 0; j < c23; j++) acc += pr[j] * sm[A_Vb + j*HH + h];
            float hv = tanhf(acc);
            g_h23[((size_t)bt*MAXM + i)*HH + h] = hv;
            atomicMax(OM + h, fenc(hv));
        }
    }
    // ---- S6: non-hit GRU rows (h_prev = 0) + om1nh ----
    {
        unsigned* OM1 = (unsigned*)(sm + A_OM1);
        for (int task = tid; task < c1*HH; task += NTA) {
            int r = task / HH, h = task - r*HH;
            if (!hitA[r]) {
                const float* gir = g_gi + ((size_t)bt*MAXM + r)*G3;
                float rr = 1.f / (1.f + __expf(-(gir[h]       + sm[A_BH + h])));
                float zz = 1.f / (1.f + __expf(-(gir[150 + h] + sm[A_BH + 150 + h])));
                float nn = tanhf(gir[300 + h] + rr * sm[A_BH + 300 + h]);
                float hv = (1.f - zz) * nn;
                g_hm1[((size_t)bt*MAXM + r)*HH + h] = hv;
                atomicMax(OM1 + h, fenc(hv));
            }
        }
    }
    __syncthreads();
    for (int h = tid; h < HH; h += NTA) {
        g_om1nh[bt*152 + h] = fdec(((unsigned*)(sm + A_OM1))[h]);
        g_om23[bt*HH + h] = (t > 0 && c23 > 0) ? fdec(((unsigned*)(sm + A_OM))[h]) : 0.f;
    }
}

// ---------------- Phase B: the irreducible recurrence ----------------
__global__ void __launch_bounds__(NTB, 1) phaseB(
    const int* __restrict__ lens,
    const float* __restrict__ bh,
    const float* __restrict__ Wd, const float* __restrict__ bd,
    const float* __restrict__ context,
    const float* __restrict__ Wc, const float* __restrict__ bc,
    float* __restrict__ out)
{
    __shared__ float OUTs[T_*HH];
    __shared__ float HP[4*152];
    __shared__ float GH[4*G3];
    __shared__ float BH[G3];
    __shared__ unsigned OM[152];
    __shared__ float TMP[T_*GS];
    __shared__ float VU[T_];
    __shared__ float SCR[T_];
    __shared__ float PL[HH + 2];

    const int b = blockIdx.x, tid = threadIdx.x;

    for (int i = tid; i < G3; i += NTB) BH[i] = bh[i];
    __syncthreads();

    for (int t = 0; t < T_; t++) {
        const int bt = b*T_ + t;
        const int nh = g_nhit[bt];
        const int c1 = g_c1[bt];

        if (nh == 0) {
            for (int h = tid; h < HH; h += NTB) {
                float o1 = (c1 > 0) ? g_om1nh[bt*152 + h] : 0.f;
                OUTs[t*HH + h] = o1 + g_om23[bt*HH + h];
            }
            continue;  // disjoint OUTs region; final sync covers visibility
        }

        for (int h = tid; h < 152; h += NTB)
            OM[h] = fenc((h < HH) ? g_om1nh[bt*152 + h] : -1e30f);

        for (int c0 = 0; c0 < nh; c0 += 4) {
            int nc = min(4, nh - c0);
            // gather h_prev rows (padded with zeros)
            for (int task = tid; task < 4*152; task += NTB) {
                int g = task / 152, k = task - g*152;
                float v = 0.f;
                if (g < nc && k < HH) {
                    int meta = g_hmeta[bt*MAXM + c0 + g];
                    int srcpos = (meta >> 8) & 0xFF;
                    const float* src = (meta & (1 << 16))
                        ? g_h23 + ((size_t)(bt - 1)*MAXM + srcpos)*HH
                        : g_hm1 + ((size_t)(bt - 1)*MAXM + srcpos)*HH;
                    v = src[k];
                }
                HP[task] = v;
            }
            __syncthreads();
            // gh = h_prev @ Wh  (450 threads, 4 rows)
            if (tid < G3) {
                float a0 = 0.f, a1 = 0.f, a2 = 0.f, a3 = 0.f;
                const float4* wrow = (const float4*)(g_WhT + tid*152);
                #pragma unroll
                for (int k4 = 0; k4 < 38; k4++) {
                    float4 w = __ldg(wrow + k4);
                    float4 h0 = *(const float4*)&HP[0*152 + k4*4];
                    float4 h1 = *(const float4*)&HP[1*152 + k4*4];
                    float4 h2 = *(const float4*)&HP[2*152 + k4*4];
                    float4 h3 = *(const float4*)&HP[3*152 + k4*4];
                    a0 += w.x*h0.x + w.y*h0.y + w.z*h0.z + w.w*h0.w;
                    a1 += w.x*h1.x + w.y*h1.y + w.z*h1.z + w.w*h1.w;
                    a2 += w.x*h2.x + w.y*h2.y + w.z*h2.z + w.w*h2.w;
                    a3 += w.x*h3.x + w.y*h3.y + w.z*h3.z + w.w*h3.w;
                }
                GH[0*G3 + tid] = a0; GH[1*G3 + tid] = a1;
                GH[2*G3 + tid] = a2; GH[3*G3 + tid] = a3;
            }
            __syncthreads();
            // gates + write-back + max merge
            for (int task = tid; task < nc*HH; task += NTB) {
                int g = task / HH, h = task - g*HH;
                int meta = g_hmeta[bt*MAXM + c0 + g];
                int r = meta & 0xFF;
                const float* gir = g_gi + ((size_t)bt*MAXM + r)*G3;
                const float* ghg = GH + g*G3;
                float hp = HP[g*152 + h];
                float rr = 1.f / (1.f + __expf(-(gir[h]       + BH[h]       + ghg[h])));
                float zz = 1.f / (1.f + __expf(-(gir[150 + h] + BH[150 + h] + ghg[150 + h])));
                float nn = tanhf(gir[300 + h] + rr * (BH[300 + h] + ghg[300 + h]));
                float hv = (1.f - zz) * nn + zz * hp;
                g_hm1[((size_t)bt*MAXM + r)*HH + h] = hv;
                atomicMax(&OM[h], fenc(hv));
            }
            __syncthreads();
        }
        for (int h = tid; h < HH; h += NTB)
            OUTs[t*HH + h] = fdec(OM[h]) + g_om23[bt*HH + h];
        __syncthreads();
    }
    __syncthreads();

    // ---- visit attention ----
    for (int task = tid; task < T_*GS; task += NTB) {
        int tt = task >> 5, a = task & 31;
        float acc = __ldg(bd + a);
        const float* o = OUTs + tt*HH;
        for (int h = 0; h < HH; h++) acc += o[h] * __ldg(Wd + h*GS + a);
        TMP[task] = acc;
    }
    __syncthreads();
    if (tid < T_) {
        float acc = 0.f;
        for (int a = 0; a < GS; a++) acc += TMP[tid*GS + a] * __ldg(context + a);
        VU[tid] = acc;
    }
    __syncthreads();
    if (tid < 32) {
        int L = lens[b];
        float v = (tid < T_ && tid < L) ? VU[tid] : -1e30f;
        float mx = v;
        for (int o = 16; o; o >>= 1) mx = fmaxf(mx, __shfl_xor_sync(0xffffffffu, mx, o));
        float e = (tid < T_ && tid < L) ? __expf(v - mx) : 0.f;
        float s = e;
        for (int o = 16; o; o >>= 1) s += __shfl_xor_sync(0xffffffffu, s, o);
        if (tid < T_) SCR[tid] = e / s;
    }
    __syncthreads();
    for (int h = tid; h < HH; h += NTB) {
        float acc = 0.f;
        for (int tt = 0; tt < T_; tt++) acc += SCR[tt] * OUTs[tt*HH + h];
        PL[h] = acc;
    }
    __syncthreads();

    // ---- classifier: 256 threads x 4 outputs, float4 Wc loads ----
    if (tid < 256) {
        int o4 = tid * 4;
        float4 acc = *(const float4*)(bc + o4);
        const float4* wc4 = (const float4*)Wc + tid;
        #pragma unroll 2
        for (int h = 0; h < HH; h++) {
            float p = PL[h];
            float4 w = __ldg(wc4 + h * (ONUM/4));
            acc.x += p * w.x; acc.y += p * w.y; acc.z += p * w.z; acc.w += p * w.w;
        }
        float4 r;
        r.x = 1.f / (1.f + __expf(-acc.x));
        r.y = 1.f / (1.f + __expf(-acc.y));
        r.z = 1.f / (1.f + __expf(-acc.z));
        r.w = 1.f / (1.f + __expf(-acc.w));
        *(float4*)(out + b*ONUM + o4) = r;
    }
}

extern "C" void kernel_launch(void* const* d_in, const int* in_sizes, int n_in,
                              void* d_out, int out_size)
{
    const float* code_x    = (const float*)d_in[0];
    const float* divided   = (const float*)d_in[1];
    const float* neighbors = (const float*)d_in[2];
    const int*   lens      = (const int*)d_in[3];
    const float* adj       = (const float*)d_in[4];
    const float* c_emb     = (const float*)d_in[5];
    const float* n_emb     = (const float*)d_in[6];
    const float* u_emb     = (const float*)d_in[7];
    const float* Wg = (const float*)d_in[8];  const float* bg = (const float*)d_in[9];
    const float* Wi = (const float*)d_in[10]; const float* bi = (const float*)d_in[11];
    const float* Wh = (const float*)d_in[12]; const float* bh = (const float*)d_in[13];
    const float* Wq = (const float*)d_in[14]; const float* bq = (const float*)d_in[15];
    const float* Wk = (const float*)d_in[16]; const float* bk = (const float*)d_in[17];
    const float* Wv = (const float*)d_in[18]; const float* bv = (const float*)d_in[19];
    const float* Wd = (const float*)d_in[20]; const float* bd = (const float*)d_in[21];
    const float* context = (const float*)d_in[22];
    const float* Wc = (const float*)d_in[23]; const float* bc = (const float*)d_in[24];
    float* out = (float*)d_out;

    cudaFuncSetAttribute(phaseA, cudaFuncAttributeMaxDynamicSharedMemorySize, A_SMEM);

    phaseA<<<B_*T_, NTA, A_SMEM>>>(code_x, divided, neighbors, adj, c_emb, n_emb, u_emb,
                                   Wg, bg, Wi, bi, Wq, bq, Wk, bk, Wv, bv, Wh, bh);
    phaseB<<<B_, NTB>>>(lens, bh, Wd, bd, context, Wc, bc, out);
}

// round 7
// speedup vs baseline: 2.8010x; 1.5006x over previous
#include <cuda_runtime.h>
#include <math.h>
#include <stdint.h>

#define B_ 8
#define T_ 16
#define N_ 1024
#define CS 48
#define GS 32
#define HH 150
#define G3 450
#define ONUM 1024
#define MAXA 160
#define MAXM 80
#define NTA 256
#define NTB 512
#define NTH 512

// ------------- device scratch (no cudaMalloc allowed) -------------
__device__ float    g_gi[B_*T_*MAXM*G3];    // GRU input gates at m1 rows
__device__ float    g_h23[B_*T_*MAXM*HH];   // attention hidden at m23 rows
__device__ float    g_om23[B_*T_*HH];       // gated max-pool over m23 rows
__device__ float    g_hm1[B_*T_*MAXM*HH];   // h_m1 rows
__device__ unsigned g_om1u[B_*T_*152];      // ENCODED max over m1 rows (grows by atomics)
__device__ int      g_c1[B_*T_];
__device__ int      g_nhit[B_*T_];          // non-chain hit count
__device__ int      g_ccnt[B_*T_];          // chain hit count
__device__ int      g_hmeta[B_*T_*MAXM];    // non-chain: r | srcpos<<8 | is23<<16
__device__ int      g_cmeta[B_*T_*MAXM];    // chain:     r | srcpos<<8
__device__ float    g_WhT[G3*152];          // Wh transposed [450][152], rows padded

__device__ __forceinline__ unsigned fenc(float f){
    unsigned u = __float_as_uint(f);
    return (u & 0x80000000u) ? ~u : (u | 0x80000000u);
}
__device__ __forceinline__ float fdec(unsigned u){
    return (u & 0x80000000u) ? __uint_as_float(u ^ 0x80000000u) : __uint_as_float(~u);
}

// ---------------- Phase A smem float offsets ----------------
#define AW_G 0
#define AW_Q 1536
#define AW_K 2560
#define AW_V 3584
#define AB_G 8384
#define AB_Q 8416
#define AB_K 8448
#define AB_V 8480
#define A_OM 8640     // 160 encoded max, om23
#define A_EC 8800     // 320x48
#define A_EP 24160    // 320x48
#define A_IN 39520    // 160x48
#define A_NP 47200    // 80x48 + pad
// overlays
#define A_CO 8800
#define A_QR 13920
#define A_Qb 24160
#define A_Kb 26720
#define A_Pb 29280
#define A_Vb 39520
#define A_OM1 51520   // 152 encoded max, om1 nonhit
#define A_BH  51672   // 456 (bh)
#define A_TOTF 52128  // -> byte 208512
// shorts 208512..215648 (3568); flags 215648(80); hitA 215728(80); prevhit 215808(1024);
// cnts at 216832 (32B)
#define A_SMEM 216864

__global__ void __launch_bounds__(NTA) phaseA(
    const float* __restrict__ code_x, const float* __restrict__ divided,
    const float* __restrict__ neighbors, const float* __restrict__ adj,
    const float* __restrict__ c_emb, const float* __restrict__ n_emb,
    const float* __restrict__ u_emb,
    const float* __restrict__ Wg, const float* __restrict__ bg,
    const float* __restrict__ Wi, const float* __restrict__ bi,
    const float* __restrict__ Wq, const float* __restrict__ bq,
    const float* __restrict__ Wk, const float* __restrict__ bk,
    const float* __restrict__ Wv, const float* __restrict__ bv,
    const float* __restrict__ Wh, const float* __restrict__ bh)
{
    extern __shared__ float sm[];
    short* sh      = (short*)((char*)sm + A_TOTF*4);
    short* rowmap  = sh;              // 1024
    short* idxA    = sh + 1024;       // 160
    short* idxNb   = idxA + MAXA;
    short* idxAp   = idxNb + MAXA;
    short* idxNbp  = idxAp + MAXA;
    short* m1l     = idxNbp + MAXA;   // 80
    short* m23l    = m1l + MAXM;      // 80
    short* aiof1   = m23l + MAXM;     // 80
    short* lstC    = aiof1 + MAXM;    // 320
    short* lstP    = lstC + 2*MAXA;   // 320
    short* prevmap = lstP + 2*MAXA;   // 1024
    unsigned char* flags   = (unsigned char*)sm + 215648; // 80
    unsigned char* hitA    = flags + 80;                  // 80
    unsigned char* prevhit = hitA + 80;                   // 1024
    int* cnts      = (int*)((char*)sm + 216832);          // 8

    const int bt = blockIdx.x;
    const int t = bt & 15;
    const int tid = threadIdx.x, lane = tid & 31, wid = tid >> 5;

    // ===== region 0: init =====
    for (int i = bt*NTA + tid; i < G3*152; i += 128*NTA) {
        int j = i / 152, k = i - j*152;
        g_WhT[i] = (k < HH) ? Wh[k*G3 + j] : 0.f;
    }
    for (int i = tid; i < CS*GS; i += NTA) sm[AW_G + i] = Wg[i];
    for (int i = tid; i < GS*GS; i += NTA) { sm[AW_Q + i] = Wq[i]; sm[AW_K + i] = Wk[i]; }
    for (int i = tid; i < GS*HH; i += NTA) sm[AW_V + i] = Wv[i];
    if (tid < GS) { sm[AB_G + tid] = bg[tid]; sm[AB_Q + tid] = bq[tid]; sm[AB_K + tid] = bk[tid]; }
    for (int i = tid; i < HH; i += NTA) sm[AB_V + i] = bv[i];
    for (int i = tid; i < G3; i += NTA) sm[A_BH + i] = bh[i];
    {
        unsigned negenc = fenc(-1e30f);
        for (int i = tid; i < 160; i += NTA) ((unsigned*)(sm + A_OM))[i] = negenc;
        for (int i = tid; i < 152; i += NTA) ((unsigned*)(sm + A_OM1))[i] = negenc;
    }
    for (int i = tid; i < N_; i += NTA) { prevmap[i] = -1; prevhit[i] = 0; }
    __syncthreads();

    // ===== region 1: ballots =====
    if (wid == 0) {
        int cAa = 0, cNbv = 0, cc1 = 0, cc23 = 0;
        const int base0 = bt * N_;
        const unsigned lt = (1u << lane) - 1u;
        for (int base = 0; base < N_; base += 32) {
            int n = base + lane;
            float cx  = code_x[base0 + n];
            float m1v = divided[(base0 + n)*3 + 0];
            float m2v = divided[(base0 + n)*3 + 1];
            float m3v = divided[(base0 + n)*3 + 2];
            float nbv = neighbors[base0 + n];
            unsigned mk = __ballot_sync(0xffffffffu, cx > 0.f);
            if (cx > 0.f) { int p = cAa + __popc(mk & lt); if (p < MAXA) { idxA[p] = (short)n; rowmap[n] = (short)p; } }
            cAa += __popc(mk);
            mk = __ballot_sync(0xffffffffu, nbv > 0.f);
            if (nbv > 0.f) { int p = cNbv + __popc(mk & lt); if (p < MAXA) idxNb[p] = (short)n; }
            cNbv += __popc(mk);
            mk = __ballot_sync(0xffffffffu, m1v > 0.f);
            if (m1v > 0.f) { int p = cc1 + __popc(mk & lt); if (p < MAXM) m1l[p] = (short)n; }
            cc1 += __popc(mk);
            bool e23 = (m2v > 0.f) || (m3v > 0.f);
            mk = __ballot_sync(0xffffffffu, e23);
            if (e23) { int p = cc23 + __popc(mk & lt); if (p < MAXM) { m23l[p] = (short)n; flags[p] = (m2v > 0.f) ? 1 : 0; } }
            cc23 += __popc(mk);
        }
        if (lane == 0) { cnts[0] = min(cAa, MAXA); cnts[1] = min(cNbv, MAXA);
                         cnts[4] = min(cc1, MAXM); cnts[5] = min(cc23, MAXM); }
    } else if (wid == 1) {
        if (t > 0) {
            int cAp = 0, cNbp = 0;
            const int base0 = (bt - 1) * N_;
            const unsigned lt = (1u << lane) - 1u;
            for (int base = 0; base < N_; base += 32) {
                int n = base + lane;
                float cx  = code_x[base0 + n];
                float nbv = neighbors[base0 + n];
                unsigned mk = __ballot_sync(0xffffffffu, cx > 0.f);
                if (cx > 0.f) { int p = cAp + __popc(mk & lt); if (p < MAXA) idxAp[p] = (short)n; }
                cAp += __popc(mk);
                mk = __ballot_sync(0xffffffffu, nbv > 0.f);
                if (nbv > 0.f) { int p = cNbp + __popc(mk & lt); if (p < MAXA) idxNbp[p] = (short)n; }
                cNbp += __popc(mk);
            }
            if (lane == 0) { cnts[2] = min(cAp, MAXA); cnts[3] = min(cNbp, MAXA); }
        } else if (lane == 0) { cnts[2] = 0; cnts[3] = 0; }
    } else if (wid == 2 && t > 0) {
        // prevmap: prev-step m1 positions; prev-step m23 positions (valid only t>=2)
        int p1 = 0, p23 = 0;
        const int base0 = (bt - 1) * N_;
        const unsigned lt = (1u << lane) - 1u;
        for (int base = 0; base < N_; base += 32) {
            int n = base + lane;
            float m1v = divided[(base0 + n)*3 + 0];
            float m2v = divided[(base0 + n)*3 + 1];
            float m3v = divided[(base0 + n)*3 + 2];
            bool b1 = m1v > 0.f;
            bool b23 = (m2v > 0.f) || (m3v > 0.f);
            unsigned mk = __ballot_sync(0xffffffffu, b1);
            if (b1) { int p = p1 + __popc(mk & lt); if (p < MAXM) prevmap[n] = (short)p; }
            p1 += __popc(mk);
            mk = __ballot_sync(0xffffffffu, b23);
            if (b23) { int p = p23 + __popc(mk & lt); if (p < MAXM && t >= 2) prevmap[n] = (short)(p | 0x4000); }
            p23 += __popc(mk);
        }
    } else if (wid == 3 && t >= 2) {
        // prevhit[n]: was node n a HIT at step t-1?  (m1_{t-1} check is applied at use site)
        const int base0 = (bt - 2) * N_;
        for (int n = lane; n < N_; n += 32) {
            float m1v = divided[(base0 + n)*3 + 0];
            float m2v = divided[(base0 + n)*3 + 1];
            float m3v = divided[(base0 + n)*3 + 2];
            prevhit[n] = (m1v > 0.f) || (((m2v > 0.f) || (m3v > 0.f)) && t >= 3);
        }
    }
    __syncthreads();

    const int cA = cnts[0], cNb = cnts[1], cAp = cnts[2], cNbp = cnts[3];
    const int c1 = cnts[4], c23 = cnts[5];
    const int totC = cA + cNb, totP = cAp + cNbp;

    // ===== region 2: hit classification + compaction (warp 0), staging =====
    if (wid == 0) {
        int nnc = 0, ncc = 0;
        const unsigned lt = (1u << lane) - 1u;
        for (int base = 0; base < c1; base += 32) {
            int r = base + lane;
            int n = (r < c1) ? m1l[r] : 0;
            short pm = (r < c1) ? prevmap[n] : (short)-1;
            bool hit = pm >= 0;
            bool is23 = hit && (pm & 0x4000);
            bool chain = hit && !is23 && prevhit[n];
            bool nonch = hit && !chain;
            unsigned mk1 = __ballot_sync(0xffffffffu, nonch);
            unsigned mk2 = __ballot_sync(0xffffffffu, chain);
            if (r < c1) {
                int srcpos = pm & 0x3FFF;
                if (nonch) {
                    int p = nnc + __popc(mk1 & lt);
                    g_hmeta[bt*MAXM + p] = r | (srcpos << 8) | ((is23 ? 1 : 0) << 16);
                }
                if (chain) {
                    int p = ncc + __popc(mk2 & lt);
                    g_cmeta[bt*MAXM + p] = r | (srcpos << 8);
                }
                hitA[r] = hit ? 1 : 0;
            }
            nnc += __popc(mk1); ncc += __popc(mk2);
        }
        if (lane == 0) { g_nhit[bt] = nnc; g_ccnt[bt] = ncc; g_c1[bt] = c1; }
    }
    if (t > 0)
        for (int i = tid; i < c23; i += NTA)
            if ((flags[i] & 1) && neighbors[(bt - 1)*N_ + m23l[i]] > 0.f) flags[i] |= 2;
    {
        int c1p = (c1 + 7) & ~7;
        for (int i = tid; i < c1p; i += NTA) aiof1[i] = (i < c1) ? rowmap[m1l[i]] : (short)0;
    }
    for (int i = tid; i < totC; i += NTA) lstC[i] = (i < cA) ? idxA[i] : idxNb[i - cA];
    if (t > 0)
        for (int i = tid; i < totP; i += NTA) lstP[i] = (i < cAp) ? idxAp[i] : idxNbp[i - cAp];
    for (int task = tid; task < totC*CS; task += NTA) {
        int j = task / CS, c = task - j*CS;
        int n = (j < cA) ? idxA[j] : idxNb[j - cA];
        sm[A_EC + task] = (j < cA) ? c_emb[n*CS + c] : n_emb[n*CS + c];
    }
    if (t > 0)
        for (int task = tid; task < totP*CS; task += NTA) {
            int j = task / CS, c = task - j*CS;
            int n = (j < cAp) ? idxAp[j] : idxNbp[j - cAp];
            sm[A_EP + task] = (j < cAp) ? c_emb[n*CS + c] : n_emb[n*CS + c];
        }
    __syncthreads();

    // ---- S1: aggregation input at active rows (batch-8 prefetch) ----
    for (int task = tid; task < cA*4; task += NTA) {
        int ai = task >> 2, ch = (task & 3) * 12;
        const float* arow = adj + (size_t)idxA[ai] * N_;
        float acc[12];
        const float* e0 = sm + A_EC + ai*CS + ch;
        #pragma unroll
        for (int c = 0; c < 12; c++) acc[c] = e0[c];
        for (int j0 = 0; j0 < totC; j0 += 8) {
            float av[8];
            #pragma unroll
            for (int u = 0; u < 8; u++) {
                int j = j0 + u;
                av[u] = (j < totC) ? __ldg(arow + lstC[j]) : 0.f;
            }
            #pragma unroll
            for (int u = 0; u < 8; u++) {
                if (av[u] != 0.f) {
                    const float* er = sm + A_EC + (j0 + u)*CS + ch;
                    #pragma unroll
                    for (int c = 0; c < 12; c++) acc[c] += av[u] * er[c];
                }
            }
        }
        float* o = sm + A_IN + ai*CS + ch;
        #pragma unroll
        for (int c = 0; c < 12; c++) o[c] = acc[c];
    }
    // ---- S1b: no_{t-1} input at m2 rows ----
    if (t > 0)
        for (int task = tid; task < c23*4; task += NTA) {
            int mi = task >> 2, ch = (task & 3) * 12;
            float acc[12];
            #pragma unroll
            for (int c = 0; c < 12; c++) acc[c] = 0.f;
            if (flags[mi] & 2) {
                int m = m23l[mi];
                const float* arow = adj + (size_t)m * N_;
                const float* nr = n_emb + m*CS + ch;
                #pragma unroll
                for (int c = 0; c < 12; c++) acc[c] = nr[c];
                for (int j0 = 0; j0 < totP; j0 += 8) {
                    float av[8];
                    #pragma unroll
                    for (int u = 0; u < 8; u++) {
                        int j = j0 + u;
                        av[u] = (j < totP) ? __ldg(arow + lstP[j]) : 0.f;
                    }
                    #pragma unroll
                    for (int u = 0; u < 8; u++) {
                        if (av[u] != 0.f) {
                            const float* er = sm + A_EP + (j0 + u)*CS + ch;
                            #pragma unroll
                            for (int c = 0; c < 12; c++) acc[c] += av[u] * er[c];
                        }
                    }
                }
            }
            float* o = sm + A_NP + mi*CS + ch;
            #pragma unroll
            for (int c = 0; c < 12; c++) o[c] = acc[c];
        }
    __syncthreads();

    // ---- S2: co = lrelu(in48 @ Wg + bg); qrows ----
    for (int task = tid; task < cA*GS; task += NTA) {
        int ai = task >> 5, g = task & 31;
        float acc = sm[AB_G + g];
        const float* in = sm + A_IN + ai*CS;
        #pragma unroll 8
        for (int c = 0; c < CS; c++) acc += in[c] * sm[AW_G + c*GS + g];
        sm[A_CO + task] = acc > 0.f ? acc : 0.01f * acc;
    }
    if (t > 0)
        for (int task = tid; task < c23*GS; task += NTA) {
            int mi = task >> 5, g = task & 31;
            float v;
            if (flags[mi] & 1) {
                float acc = sm[AB_G + g];
                const float* in = sm + A_NP + mi*CS;
                #pragma unroll 8
                for (int c = 0; c < CS; c++) acc += in[c] * sm[AW_G + c*GS + g];
                v = acc > 0.f ? acc : 0.01f * acc;
            } else {
                v = u_emb[m23l[mi]*GS + g];
            }
            sm[A_QR + task] = v;
        }
    __syncthreads();

    // ---- S3: gi at m1 rows; q/k/v (t>0) ----
    if (c1 > 0) {
        int ng = (c1 + 7) >> 3;
        for (int task = tid; task < G3*ng; task += NTA) {
            int j = task % G3, grp = task / G3, r0 = grp * 8;
            float acc[8];
            int ai[8];
            #pragma unroll
            for (int g = 0; g < 8; g++) { acc[g] = 0.f; ai[g] = aiof1[r0 + g]; }
            for (int c = 0; c < GS; c++) {
                float w = __ldg(Wi + c*G3 + j);
                #pragma unroll
                for (int g = 0; g < 8; g++) acc[g] += sm[A_CO + ai[g]*GS + c] * w;
            }
            float bij = __ldg(bi + j);
            int nr = min(8, c1 - r0);
            #pragma unroll
            for (int g = 0; g < 8; g++)
                if (g < nr) g_gi[((size_t)bt*MAXM + r0 + g)*G3 + j] = acc[g] + bij;
        }
    }
    if (t > 0 && c23 > 0) {
        for (int task = tid; task < c23*GS; task += NTA) {
            int i = task >> 5, a = task & 31;
            const float* qr = sm + A_QR + i*GS;
            int ai = rowmap[m23l[i]];
            const float* co = sm + A_CO + ai*GS;
            float accq = sm[AB_Q + a], acck = sm[AB_K + a];
            #pragma unroll
            for (int g = 0; g < GS; g++) {
                accq += qr[g] * sm[AW_Q + g*GS + a];
                acck += co[g] * sm[AW_K + g*GS + a];
            }
            sm[A_Qb + task] = accq;
            sm[A_Kb + task] = acck;
        }
        for (int task = tid; task < c23*HH; task += NTA) {
            int i = task / HH, h = task - i*HH;
            const float* qr = sm + A_QR + i*GS;
            float acc = sm[AB_V + h];
            #pragma unroll
            for (int g = 0; g < GS; g++) acc += qr[g] * sm[AW_V + g*HH + h];
            sm[A_Vb + i*HH + h] = acc;
        }
    }
    __syncthreads();

    // ---- S4: scores + softmax (warp per query) ----
    if (t > 0 && c23 > 0) {
        const float scale = 0.17677669529663687f;
        for (int i = wid; i < c23; i += 8) {
            const float* qi = sm + A_Qb + i*GS;
            float mx = -1e30f;
            for (int j = lane; j < c23; j += 32) {
                const float* kj = sm + A_Kb + j*GS;
                float s = 0.f;
                #pragma unroll
                for (int g = 0; g < GS; g++) s += qi[g] * kj[g];
                s *= scale;
                sm[A_Pb + i*MAXM + j] = s;
                mx = fmaxf(mx, s);
            }
            for (int o = 16; o; o >>= 1) mx = fmaxf(mx, __shfl_xor_sync(0xffffffffu, mx, o));
            float sum = 0.f;
            for (int j = lane; j < c23; j += 32) {
                float e = __expf(sm[A_Pb + i*MAXM + j] - mx);
                sm[A_Pb + i*MAXM + j] = e; sum += e;
            }
            for (int o = 16; o; o >>= 1) sum += __shfl_xor_sync(0xffffffffu, sum, o);
            float inv = 1.f / sum;
            for (int j = lane; j < c23; j += 32) sm[A_Pb + i*MAXM + j] *= inv;
        }
    }
    __syncthreads();

    // ---- S5: h_m23 + om23 ----
    if (t > 0 && c23 > 0) {
        unsigned* OM = (unsigned*)(sm + A_OM);
        for (int task = tid; task < c23*HH; task += NTA) {
            int i = task / HH, h = task - i*HH;
            float acc = 0.f;
            const float* pr = sm + A_Pb + i*MAXM;
            for (int j = 0; j < c23; j++) acc += pr[j] * sm[A_Vb + j*HH + h];
            float hv = tanhf(acc);
            g_h23[((size_t)bt*MAXM + i)*HH + h] = hv;
            atomicMax(OM + h, fenc(hv));
        }
    }
    // ---- S6: non-hit GRU rows (h_prev = 0) + om1 (encoded) ----
    {
        unsigned* OM1 = (unsigned*)(sm + A_OM1);
        for (int task = tid; task < c1*HH; task += NTA) {
            int r = task / HH, h = task - r*HH;
            if (!hitA[r]) {
                const float* gir = g_gi + ((size_t)bt*MAXM + r)*G3;
                float rr = 1.f / (1.f + __expf(-(gir[h]       + sm[A_BH + h])));
                float zz = 1.f / (1.f + __expf(-(gir[150 + h] + sm[A_BH + 150 + h])));
                float nn = tanhf(gir[300 + h] + rr * sm[A_BH + 300 + h]);
                float hv = (1.f - zz) * nn;
                g_hm1[((size_t)bt*MAXM + r)*HH + h] = hv;
                atomicMax(OM1 + h, fenc(hv));
            }
        }
    }
    __syncthreads();
    for (int h = tid; h < HH; h += NTA) {
        g_om1u[bt*152 + h] = ((unsigned*)(sm + A_OM1))[h];
        g_om23[bt*HH + h] = (t > 0 && c23 > 0) ? fdec(((unsigned*)(sm + A_OM))[h]) : 0.f;
    }
}

// ---------------- Phase H: non-chain hits, fully parallel over (b,t) ----------------
__global__ void __launch_bounds__(NTH) phaseH(const float* __restrict__ bh)
{
    __shared__ float HP[4*152];
    __shared__ float GH[4*G3];
    __shared__ float BH[G3];

    const int bt = blockIdx.x, tid = threadIdx.x;
    const int nh = g_nhit[bt];
    if (nh == 0) return;
    for (int i = tid; i < G3; i += NTH) BH[i] = bh[i];
    __syncthreads();

    for (int c0 = 0; c0 < nh; c0 += 4) {
        int nc = min(4, nh - c0);
        for (int task = tid; task < 4*152; task += NTH) {
            int g = task / 152, k = task - g*152;
            float v = 0.f;
            if (g < nc && k < HH) {
                int meta = g_hmeta[bt*MAXM + c0 + g];
                int srcpos = (meta >> 8) & 0xFF;
                const float* src = (meta & (1 << 16))
                    ? g_h23 + ((size_t)(bt - 1)*MAXM + srcpos)*HH
                    : g_hm1 + ((size_t)(bt - 1)*MAXM + srcpos)*HH;
                v = src[k];
            }
            HP[task] = v;
        }
        __syncthreads();
        if (tid < G3) {
            float a0 = 0.f, a1 = 0.f, a2 = 0.f, a3 = 0.f;
            const float4* wrow = (const float4*)(g_WhT + tid*152);
            #pragma unroll
            for (int k4 = 0; k4 < 38; k4++) {
                float4 w = __ldg(wrow + k4);
                float4 h0 = *(const float4*)&HP[0*152 + k4*4];
                float4 h1 = *(const float4*)&HP[1*152 + k4*4];
                float4 h2 = *(const float4*)&HP[2*152 + k4*4];
                float4 h3 = *(const float4*)&HP[3*152 + k4*4];
                a0 += w.x*h0.x + w.y*h0.y + w.z*h0.z + w.w*h0.w;
                a1 += w.x*h1.x + w.y*h1.y + w.z*h1.z + w.w*h1.w;
                a2 += w.x*h2.x + w.y*h2.y + w.z*h2.z + w.w*h2.w;
                a3 += w.x*h3.x + w.y*h3.y + w.z*h3.z + w.w*h3.w;
            }
            GH[0*G3 + tid] = a0; GH[1*G3 + tid] = a1;
            GH[2*G3 + tid] = a2; GH[3*G3 + tid] = a3;
        }
        __syncthreads();
        for (int task = tid; task < nc*HH; task += NTH) {
            int g = task / HH, h = task - g*HH;
            int meta = g_hmeta[bt*MAXM + c0 + g];
            int r = meta & 0xFF;
            const float* gir = g_gi + ((size_t)bt*MAXM + r)*G3;
            const float* ghg = GH + g*G3;
            float hp = HP[g*152 + h];
            float rr = 1.f / (1.f + __expf(-(gir[h]       + BH[h]       + ghg[h])));
            float zz = 1.f / (1.f + __expf(-(gir[150 + h] + BH[150 + h] + ghg[150 + h])));
            float nn = tanhf(gir[300 + h] + rr * (BH[300 + h] + ghg[300 + h]));
            float hv = (1.f - zz) * nn + zz * hp;
            g_hm1[((size_t)bt*MAXM + r)*HH + h] = hv;
            atomicMax(&g_om1u[bt*152 + h], fenc(hv));
        }
        __syncthreads();
    }
}

// ---------------- Phase B: chain hits (rare) + attention + classifier ----------------
__global__ void __launch_bounds__(NTB, 1) phaseB(
    const int* __restrict__ lens,
    const float* __restrict__ bh,
    const float* __restrict__ Wd, const float* __restrict__ bd,
    const float* __restrict__ context,
    const float* __restrict__ Wc, const float* __restrict__ bc,
    float* __restrict__ out)
{
    __shared__ float OUTs[T_*HH];
    __shared__ float HP[152];
    __shared__ float GH[G3];
    __shared__ float BH[G3];
    __shared__ unsigned OM[152];
    __shared__ float TMP[T_*GS];
    __shared__ float VU[T_];
    __shared__ float SCR[T_];
    __shared__ float PL[HH + 2];

    const int b = blockIdx.x, tid = threadIdx.x;

    for (int i = tid; i < G3; i += NTB) BH[i] = bh[i];
    __syncthreads();

    for (int t = 0; t < T_; t++) {
        const int bt = b*T_ + t;
        const int cc = g_ccnt[bt];
        const int c1 = g_c1[bt];

        if (cc == 0) {
            // common path: no recurrence work — pure read-combine, no syncs
            for (int h = tid; h < HH; h += NTB) {
                float o1 = (c1 > 0) ? fdec(g_om1u[bt*152 + h]) : 0.f;
                OUTs[t*HH + h] = o1 + g_om23[bt*HH + h];
            }
            continue;
        }

        for (int h = tid; h < 152; h += NTB) OM[h] = g_om1u[bt*152 + h];
        __syncthreads();

        for (int ci = 0; ci < cc; ci++) {
            int meta = g_cmeta[bt*MAXM + ci];
            int r = meta & 0xFF, srcpos = (meta >> 8) & 0xFF;
            const float* src = g_hm1 + ((size_t)(bt - 1)*MAXM + srcpos)*HH;
            for (int k = tid; k < 152; k += NTB) HP[k] = (k < HH) ? src[k] : 0.f;
            __syncthreads();
            if (tid < G3) {
                float a0 = 0.f;
                const float4* wrow = (const float4*)(g_WhT + tid*152);
                #pragma unroll
                for (int k4 = 0; k4 < 38; k4++) {
                    float4 w = __ldg(wrow + k4);
                    float4 h0 = *(const float4*)&HP[k4*4];
                    a0 += w.x*h0.x + w.y*h0.y + w.z*h0.z + w.w*h0.w;
                }
                GH[tid] = a0;
            }
            __syncthreads();
            if (tid < HH) {
                int h = tid;
                const float* gir = g_gi + ((size_t)bt*MAXM + r)*G3;
                float hp = HP[h];
                float rr = 1.f / (1.f + __expf(-(gir[h]       + BH[h]       + GH[h])));
                float zz = 1.f / (1.f + __expf(-(gir[150 + h] + BH[150 + h] + GH[150 + h])));
                float nn = tanhf(gir[300 + h] + rr * (BH[300 + h] + GH[300 + h]));
                float hv = (1.f - zz) * nn + zz * hp;
                g_hm1[((size_t)bt*MAXM + r)*HH + h] = hv;
                atomicMax(&OM[h], fenc(hv));
            }
            __syncthreads();
        }
        for (int h = tid; h < HH; h += NTB)
            OUTs[t*HH + h] = fdec(OM[h]) + g_om23[bt*HH + h];
        __syncthreads();
    }
    __syncthreads();

    // ---- visit attention ----
    for (int task = tid; task < T_*GS; task += NTB) {
        int tt = task >> 5, a = task & 31;
        float acc = __ldg(bd + a);
        const float* o = OUTs + tt*HH;
        for (int h = 0; h < HH; h++) acc += o[h] * __ldg(Wd + h*GS + a);
        TMP[task] = acc;
    }
    __syncthreads();
    if (tid < T_) {
        float acc = 0.f;
        for (int a = 0; a < GS; a++) acc += TMP[tid*GS + a] * __ldg(context + a);
        VU[tid] = acc;
    }
    __syncthreads();
    if (tid < 32) {
        int L = lens[b];
        float v = (tid < T_ && tid < L) ? VU[tid] : -1e30f;
        float mx = v;
        for (int o = 16; o; o >>= 1) mx = fmaxf(mx, __shfl_xor_sync(0xffffffffu, mx, o));
        float e = (tid < T_ && tid < L) ? __expf(v - mx) : 0.f;
        float s = e;
        for (int o = 16; o; o >>= 1) s += __shfl_xor_sync(0xffffffffu, s, o);
        if (tid < T_) SCR[tid] = e / s;
    }
    __syncthreads();
    for (int h = tid; h < HH; h += NTB) {
        float acc = 0.f;
        for (int tt = 0; tt < T_; tt++) acc += SCR[tt] * OUTs[tt*HH + h];
        PL[h] = acc;
    }
    __syncthreads();

    if (tid < 256) {
        int o4 = tid * 4;
        float4 acc = *(const float4*)(bc + o4);
        const float4* wc4 = (const float4*)Wc + tid;
        #pragma unroll 2
        for (int h = 0; h < HH; h++) {
            float p = PL[h];
            float4 w = __ldg(wc4 + h * (ONUM/4));
            acc.x += p * w.x; acc.y += p * w.y; acc.z += p * w.z; acc.w += p * w.w;
        }
        float4 r;
        r.x = 1.f / (1.f + __expf(-acc.x));
        r.y = 1.f / (1.f + __expf(-acc.y));
        r.z = 1.f / (1.f + __expf(-acc.z));
        r.w = 1.f / (1.f + __expf(-acc.w));
        *(float4*)(out + b*ONUM + o4) = r;
    }
}

extern "C" void kernel_launch(void* const* d_in, const int* in_sizes, int n_in,
                              void* d_out, int out_size)
{
    const float* code_x    = (const float*)d_in[0];
    const float* divided   = (const float*)d_in[1];
    const float* neighbors = (const float*)d_in[2];
    const int*   lens      = (const int*)d_in[3];
    const float* adj       = (const float*)d_in[4];
    const float* c_emb     = (const float*)d_in[5];
    const float* n_emb     = (const float*)d_in[6];
    const float* u_emb     = (const float*)d_in[7];
    const float* Wg = (const float*)d_in[8];  const float* bg = (const float*)d_in[9];
    const float* Wi = (const float*)d_in[10]; const float* bi = (const float*)d_in[11];
    const float* Wh = (const float*)d_in[12]; const float* bh = (const float*)d_in[13];
    const float* Wq = (const float*)d_in[14]; const float* bq = (const float*)d_in[15];
    const float* Wk = (const float*)d_in[16]; const float* bk = (const float*)d_in[17];
    const float* Wv = (const float*)d_in[18]; const float* bv = (const float*)d_in[19];
    const float* Wd = (const float*)d_in[20]; const float* bd = (const float*)d_in[21];
    const float* context = (const float*)d_in[22];
    const float* Wc = (const float*)d_in[23]; const float* bc = (const float*)d_in[24];
    float* out = (float*)d_out;

    cudaFuncSetAttribute(phaseA, cudaFuncAttributeMaxDynamicSharedMemorySize, A_SMEM);

    phaseA<<<B_*T_, NTA, A_SMEM>>>(code_x, divided, neighbors, adj, c_emb, n_emb, u_emb,
                                   Wg, bg, Wi, bi, Wq, bq, Wk, bk, Wv, bv, Wh, bh);
    phaseH<<<B_*T_, NTH>>>(bh);
    phaseB<<<B_, NTB>>>(lens, bh, Wd, bd, context, Wc, bc, out);
}